// round 13
// baseline (speedup 1.0000x reference)
#include <cuda_runtime.h>
#include <cuda_bf16.h>
#include <cstdint>
#include <math.h>

#define BB 2
#define SS 2048
#define DD 1024
#define HH 16
#define HD 64
#define M_TOT (BB*SS)   // 4096

// ---------------------------------------------------------------------------
// Scratch (__device__ globals: allocation-free per harness rules)
// ---------------------------------------------------------------------------
__device__ __nv_bfloat16 g_xhi[M_TOT * DD];
__device__ __nv_bfloat16 g_xlo[M_TOT * DD];
__device__ __nv_bfloat16 g_chi[M_TOT * DD];
__device__ __nv_bfloat16 g_clo[M_TOT * DD];

__device__ __nv_bfloat16 g_qhi[M_TOT * DD];
__device__ __nv_bfloat16 g_qlo[M_TOT * DD];
__device__ __nv_bfloat16 g_khi[M_TOT * DD];
__device__ __nv_bfloat16 g_klo[M_TOT * DD];
__device__ __nv_bfloat16 g_vhi[M_TOT * DD];
__device__ __nv_bfloat16 g_vlo[M_TOT * DD];

__device__ __nv_bfloat16 g_wq_hi[DD * DD];
__device__ __nv_bfloat16 g_wq_lo[DD * DD];
__device__ __nv_bfloat16 g_wk_hi[DD * DD];
__device__ __nv_bfloat16 g_wk_lo[DD * DD];
__device__ __nv_bfloat16 g_wv_hi[DD * DD];
__device__ __nv_bfloat16 g_wv_lo[DD * DD];
__device__ __nv_bfloat16 g_wo_hi[DD * DD];
__device__ __nv_bfloat16 g_wo_lo[DD * DD];

// ---------------------------------------------------------------------------
// helpers
// ---------------------------------------------------------------------------
__device__ __forceinline__ uint32_t smem_u32(const void* p) {
    uint32_t a;
    asm("{ .reg .u64 t; cvta.to.shared.u64 t, %1; cvt.u32.u64 %0, t; }" : "=r"(a) : "l"(p));
    return a;
}
__device__ __forceinline__ void ldmatrix_x4(uint32_t& r0, uint32_t& r1, uint32_t& r2,
                                            uint32_t& r3, uint32_t addr) {
    asm volatile("ldmatrix.sync.aligned.m8n8.x4.shared.b16 {%0,%1,%2,%3}, [%4];"
                 : "=r"(r0), "=r"(r1), "=r"(r2), "=r"(r3) : "r"(addr));
}
__device__ __forceinline__ void ldmatrix_x4_trans(uint32_t& r0, uint32_t& r1, uint32_t& r2,
                                                  uint32_t& r3, uint32_t addr) {
    asm volatile("ldmatrix.sync.aligned.m8n8.x4.trans.shared.b16 {%0,%1,%2,%3}, [%4];"
                 : "=r"(r0), "=r"(r1), "=r"(r2), "=r"(r3) : "r"(addr));
}
__device__ __forceinline__ void mma_bf16(float* d, const uint32_t* a, const uint32_t* b) {
    asm volatile(
        "mma.sync.aligned.m16n8k16.row.col.f32.bf16.bf16.f32 "
        "{%0,%1,%2,%3}, {%4,%5,%6,%7}, {%8,%9}, {%0,%1,%2,%3};"
        : "+f"(d[0]), "+f"(d[1]), "+f"(d[2]), "+f"(d[3])
        : "r"(a[0]), "r"(a[1]), "r"(a[2]), "r"(a[3]), "r"(b[0]), "r"(b[1]));
}
// fast raw exp2 (args <= 0, bounded; -inf -> 0)
__device__ __forceinline__ float ex2(float x) {
    float r;
    asm("ex2.approx.ftz.f32 %0, %1;" : "=f"(r) : "f"(x));
    return r;
}
// fast split: pack (x,y) into bf16x2 hi-pair + residual lo-pair
__device__ __forceinline__ void split2(float x, float y, uint32_t& hi, uint32_t& lo) {
    asm("cvt.rn.bf16x2.f32 %0, %1, %2;" : "=r"(hi) : "f"(y), "f"(x));
    float hx = __uint_as_float(hi << 16);
    float hy = __uint_as_float(hi & 0xffff0000u);
    asm("cvt.rn.bf16x2.f32 %0, %1, %2;" : "=r"(lo) : "f"(y - hy), "f"(x - hx));
}
#define CP16(d, s) asm volatile("cp.async.cg.shared.global [%0], [%1], 16;" :: "r"(d), "l"(s))
#define CP_COMMIT() asm volatile("cp.async.commit_group;" ::: "memory")
#define CP_WAIT0()  asm volatile("cp.async.wait_group 0;" ::: "memory")
// SW128 swizzle: XOR 16B-sector index with row-within-8 (1024B atoms)
#define SWZ(b) ((uint32_t)(b) ^ ((((uint32_t)(b)) >> 3) & 0x70u))

// ---------------------------------------------------------------------------
// fp32 -> bf16 hi/lo split (elementwise, vectorized)
// ---------------------------------------------------------------------------
__global__ void cvt_split4(const float4* __restrict__ in,
                           __nv_bfloat162* __restrict__ hi,
                           __nv_bfloat162* __restrict__ lo, int n4) {
    int i = blockIdx.x * blockDim.x + threadIdx.x;
    if (i >= n4) return;
    float4 v = in[i];
    uint32_t h0, l0, h1, l1;
    split2(v.x, v.y, h0, l0);
    split2(v.z, v.w, h1, l1);
    ((uint32_t*)hi)[2*i]   = h0;
    ((uint32_t*)hi)[2*i+1] = h1;
    ((uint32_t*)lo)[2*i]   = l0;
    ((uint32_t*)lo)[2*i+1] = l1;
}

// ---------------------------------------------------------------------------
// W[K][N] fp32 -> transposed bf16 hi/lo [N][K]; 4 weights in one launch
// ---------------------------------------------------------------------------
struct WJob { const float* W; __nv_bfloat16* hiT; __nv_bfloat16* loT; };

__global__ void cvt_wT4(WJob j0, WJob j1, WJob j2, WJob j3) {
    __shared__ float t[32][33];
    WJob j = (blockIdx.z == 0) ? j0 : (blockIdx.z == 1) ? j1 : (blockIdx.z == 2) ? j2 : j3;
    int n0 = blockIdx.x * 32, k0 = blockIdx.y * 32;
    int tx = threadIdx.x, ty = threadIdx.y;
    #pragma unroll
    for (int r = 0; r < 32; r += 8)
        t[ty + r][tx] = j.W[(size_t)(k0 + ty + r) * DD + n0 + tx];
    __syncthreads();
    #pragma unroll
    for (int r = 0; r < 32; r += 8) {
        float v = t[tx][ty + r];
        __nv_bfloat16 h = __float2bfloat16(v);
        __nv_bfloat16 l = __float2bfloat16(v - __bfloat162float(h));
        size_t o = (size_t)(n0 + ty + r) * DD + k0 + tx;   // [n][k]
        j.hiT[o] = h; j.loT[o] = l;
    }
}

// ---------------------------------------------------------------------------
// GEMM common geometry
// ---------------------------------------------------------------------------
#define CTA_M 128
#define CTA_N 128
#define KC 32
#define LDT 40
#define TILE_ELEMS (128 * LDT)
#define G_TILE_B (TILE_ELEMS * 2)          // 10240 B
#define G_STAGE_B (4 * G_TILE_B)           // 40960 B
#define SMEM_GEMM (2 * G_STAGE_B)          // 81920 B

// ---------------------------------------------------------------------------
// Fused QKV GEMM: one launch, proj = blockIdx.x / 8. Writes bf16 hi/lo pairs.
// ---------------------------------------------------------------------------
struct QKVJob {
    const __nv_bfloat16* bhi[3];
    const __nv_bfloat16* blo[3];
    const float*         bias[3];
    uint32_t*            chi[3];
    uint32_t*            clo[3];
    float                scale[3];
};

__global__ void __launch_bounds__(256, 2) gemm_qkv(
    const __nv_bfloat16* __restrict__ Ahi, const __nv_bfloat16* __restrict__ Alo,
    QKVJob job, int M, int N, int K) {
    extern __shared__ __nv_bfloat16 smG[];
    const uint32_t sbase = smem_u32(smG);

    const int proj = blockIdx.x >> 3;
    const __nv_bfloat16* __restrict__ BhiT = job.bhi[proj];
    const __nv_bfloat16* __restrict__ BloT = job.blo[proj];
    const float* __restrict__ bias = job.bias[proj];
    uint32_t* __restrict__ Chi2 = job.chi[proj];
    uint32_t* __restrict__ Clo2 = job.clo[proj];
    const float scale = job.scale[proj];

    const int tid  = threadIdx.x;
    const int wid  = tid >> 5;
    const int lane = tid & 31;
    const int warp_m = wid & 1;
    const int warp_n = wid >> 1;
    const int m0 = blockIdx.y * CTA_M;
    const int n0 = (blockIdx.x & 7) * CTA_N;

    float acc[4][4][4];
    #pragma unroll
    for (int i = 0; i < 4; i++)
        #pragma unroll
        for (int j = 0; j < 4; j++)
            #pragma unroll
            for (int e = 0; e < 4; e++) acc[i][j][e] = 0.f;

    const int lm_r  = lane & 7;
    const int lm_m4 = lane >> 3;
    const int a_row = warp_m * 64 + (lm_m4 & 1) * 8 + lm_r;
    const int a_kof = (lm_m4 >> 1) * 8;
    const int b_row4 = warp_n * 32 + (lane >> 4) * 8 + lm_r;
    const int b_kof4 = ((lane >> 3) & 1) * 8;

    const int ld_row = tid >> 2, ld_s = tid & 3;
    const int nchunks = K / KC;

    #define G_PREFETCH(stage, k0_)  do {                                              \
        uint32_t dstb = sbase + (uint32_t)(stage) * G_STAGE_B;                        \
        _Pragma("unroll")                                                             \
        for (int t = 0; t < 2; t++) {                                                 \
            int row = ld_row + t * 64;                                                \
            uint32_t so = (uint32_t)(row * LDT + ld_s * 8) * 2;                       \
            CP16(dstb + so,               Ahi  + (size_t)(m0 + row) * K + (k0_) + ld_s * 8); \
            CP16(dstb + G_TILE_B + so,    Alo  + (size_t)(m0 + row) * K + (k0_) + ld_s * 8); \
            CP16(dstb + 2*G_TILE_B + so,  BhiT + (size_t)(n0 + row) * K + (k0_) + ld_s * 8); \
            CP16(dstb + 3*G_TILE_B + so,  BloT + (size_t)(n0 + row) * K + (k0_) + ld_s * 8); \
        }                                                                             \
        CP_COMMIT();                                                                  \
    } while (0)

    G_PREFETCH(0, 0);

    for (int c = 0; c < nchunks; c++) {
        CP_WAIT0();
        __syncthreads();
        if (c + 1 < nchunks) G_PREFETCH((c + 1) & 1, (c + 1) * KC);

        const uint32_t sb = sbase + (uint32_t)(c & 1) * G_STAGE_B;
        const uint32_t sAhi = sb, sAlo = sb + G_TILE_B;
        const uint32_t sBhi = sb + 2 * G_TILE_B, sBlo = sb + 3 * G_TILE_B;

        #pragma unroll
        for (int ks = 0; ks < 2; ks++) {
            uint32_t ahi[4][4], alo[4][4], bhi[4][2], blo[4][2];
            #pragma unroll
            for (int i = 0; i < 4; i++) {
                uint32_t off = (uint32_t)((a_row + i * 16) * LDT + ks * 16 + a_kof) * 2;
                ldmatrix_x4(ahi[i][0], ahi[i][1], ahi[i][2], ahi[i][3], sAhi + off);
                ldmatrix_x4(alo[i][0], alo[i][1], alo[i][2], alo[i][3], sAlo + off);
            }
            #pragma unroll
            for (int j2 = 0; j2 < 4; j2 += 2) {
                uint32_t off = (uint32_t)((b_row4 + j2 * 8) * LDT + ks * 16 + b_kof4) * 2;
                ldmatrix_x4(bhi[j2][0], bhi[j2][1], bhi[j2+1][0], bhi[j2+1][1], sBhi + off);
                ldmatrix_x4(blo[j2][0], blo[j2][1], blo[j2+1][0], blo[j2+1][1], sBlo + off);
            }
            #pragma unroll
            for (int i = 0; i < 4; i++)
                #pragma unroll
                for (int j = 0; j < 4; j++) {
                    mma_bf16(acc[i][j], ahi[i], bhi[j]);
                    mma_bf16(acc[i][j], ahi[i], blo[j]);
                    mma_bf16(acc[i][j], alo[i], bhi[j]);
                }
        }
    }

    __syncthreads();
    const int grp = lane >> 2, tg = lane & 3;
    #pragma unroll
    for (int i = 0; i < 4; i++) {
        int row0 = m0 + warp_m * 64 + i * 16 + grp;
        #pragma unroll
        for (int j = 0; j < 4; j++) {
            int col = n0 + warp_n * 32 + j * 8 + tg * 2;
            float b0 = bias[col], b1 = bias[col + 1];
            uint32_t h2, l2;
            split2((acc[i][j][0] + b0) * scale, (acc[i][j][1] + b1) * scale, h2, l2);
            Chi2[(size_t)row0 * (N / 2) + col / 2] = h2;
            Clo2[(size_t)row0 * (N / 2) + col / 2] = l2;
            split2((acc[i][j][2] + b0) * scale, (acc[i][j][3] + b1) * scale, h2, l2);
            Chi2[(size_t)(row0 + 8) * (N / 2) + col / 2] = h2;
            Clo2[(size_t)(row0 + 8) * (N / 2) + col / 2] = l2;
        }
    }
    #undef G_PREFETCH
}

// ---------------------------------------------------------------------------
// Out-projection GEMM (fp32 output)
// ---------------------------------------------------------------------------
__global__ void __launch_bounds__(256, 2) gemm_hmma(
    const __nv_bfloat16* __restrict__ Ahi, const __nv_bfloat16* __restrict__ Alo,
    const __nv_bfloat16* __restrict__ BhiT, const __nv_bfloat16* __restrict__ BloT,
    const float* __restrict__ bias, float* __restrict__ Cf,
    int M, int N, int K) {
    extern __shared__ __nv_bfloat16 smG[];
    const uint32_t sbase = smem_u32(smG);

    const int tid  = threadIdx.x;
    const int wid  = tid >> 5;
    const int lane = tid & 31;
    const int warp_m = wid & 1;
    const int warp_n = wid >> 1;
    const int m0 = blockIdx.y * CTA_M;
    const int n0 = blockIdx.x * CTA_N;

    float acc[4][4][4];
    #pragma unroll
    for (int i = 0; i < 4; i++)
        #pragma unroll
        for (int j = 0; j < 4; j++)
            #pragma unroll
            for (int e = 0; e < 4; e++) acc[i][j][e] = 0.f;

    const int lm_r  = lane & 7;
    const int lm_m4 = lane >> 3;
    const int a_row = warp_m * 64 + (lm_m4 & 1) * 8 + lm_r;
    const int a_kof = (lm_m4 >> 1) * 8;
    const int b_row4 = warp_n * 32 + (lane >> 4) * 8 + lm_r;
    const int b_kof4 = ((lane >> 3) & 1) * 8;

    const int ld_row = tid >> 2, ld_s = tid & 3;
    const int nchunks = K / KC;

    #define G_PREFETCH(stage, k0_)  do {                                              \
        uint32_t dstb = sbase + (uint32_t)(stage) * G_STAGE_B;                        \
        _Pragma("unroll")                                                             \
        for (int t = 0; t < 2; t++) {                                                 \
            int row = ld_row + t * 64;                                                \
            uint32_t so = (uint32_t)(row * LDT + ld_s * 8) * 2;                       \
            CP16(dstb + so,               Ahi  + (size_t)(m0 + row) * K + (k0_) + ld_s * 8); \
            CP16(dstb + G_TILE_B + so,    Alo  + (size_t)(m0 + row) * K + (k0_) + ld_s * 8); \
            CP16(dstb + 2*G_TILE_B + so,  BhiT + (size_t)(n0 + row) * K + (k0_) + ld_s * 8); \
            CP16(dstb + 3*G_TILE_B + so,  BloT + (size_t)(n0 + row) * K + (k0_) + ld_s * 8); \
        }                                                                             \
        CP_COMMIT();                                                                  \
    } while (0)

    G_PREFETCH(0, 0);

    for (int c = 0; c < nchunks; c++) {
        CP_WAIT0();
        __syncthreads();
        if (c + 1 < nchunks) G_PREFETCH((c + 1) & 1, (c + 1) * KC);

        const uint32_t sb = sbase + (uint32_t)(c & 1) * G_STAGE_B;
        const uint32_t sAhi = sb, sAlo = sb + G_TILE_B;
        const uint32_t sBhi = sb + 2 * G_TILE_B, sBlo = sb + 3 * G_TILE_B;

        #pragma unroll
        for (int ks = 0; ks < 2; ks++) {
            uint32_t ahi[4][4], alo[4][4], bhi[4][2], blo[4][2];
            #pragma unroll
            for (int i = 0; i < 4; i++) {
                uint32_t off = (uint32_t)((a_row + i * 16) * LDT + ks * 16 + a_kof) * 2;
                ldmatrix_x4(ahi[i][0], ahi[i][1], ahi[i][2], ahi[i][3], sAhi + off);
                ldmatrix_x4(alo[i][0], alo[i][1], alo[i][2], alo[i][3], sAlo + off);
            }
            #pragma unroll
            for (int j2 = 0; j2 < 4; j2 += 2) {
                uint32_t off = (uint32_t)((b_row4 + j2 * 8) * LDT + ks * 16 + b_kof4) * 2;
                ldmatrix_x4(bhi[j2][0], bhi[j2][1], bhi[j2+1][0], bhi[j2+1][1], sBhi + off);
                ldmatrix_x4(blo[j2][0], blo[j2][1], blo[j2+1][0], blo[j2+1][1], sBlo + off);
            }
            #pragma unroll
            for (int i = 0; i < 4; i++)
                #pragma unroll
                for (int j = 0; j < 4; j++) {
                    mma_bf16(acc[i][j], ahi[i], bhi[j]);
                    mma_bf16(acc[i][j], ahi[i], blo[j]);
                    mma_bf16(acc[i][j], alo[i], bhi[j]);
                }
        }
    }

    __syncthreads();
    const int grp = lane >> 2, tg = lane & 3;
    #pragma unroll
    for (int i = 0; i < 4; i++) {
        int row0 = m0 + warp_m * 64 + i * 16 + grp;
        #pragma unroll
        for (int j = 0; j < 4; j++) {
            int col = n0 + warp_n * 32 + j * 8 + tg * 2;
            float b0 = bias[col], b1 = bias[col + 1];
            float* p0 = Cf + (size_t)row0 * N + col;
            p0[0] = acc[i][j][0] + b0;
            p0[1] = acc[i][j][1] + b1;
            float* p1 = Cf + (size_t)(row0 + 8) * N + col;
            p1[0] = acc[i][j][2] + b0;
            p1[1] = acc[i][j][3] + b1;
        }
    }
    #undef G_PREFETCH
}

// ---------------------------------------------------------------------------
// HMMA causal flash attention, v7: 256 threads, q-tile 128, Q in smem,
// 2-stage cp.async K/V (64-row k-tiles). regs capped at 128 -> 2 CTAs/SM
// = 16 warps/SM. Q pre-scaled by 0.125*log2(e).
// smem: [stage0 32KB][stage1 32KB][Qhi 16KB][Qlo 16KB] = 96KB.
// ---------------------------------------------------------------------------
#define A_TILE_B 8192                      // 64 rows * 128 B (K/V tiles)
#define A_STAGE_B (4 * A_TILE_B)           // 32768 B
#define AQ_TILE_B 16384                    // 128 rows * 128 B (Q tile)
#define SMEM_ATTN (2 * A_STAGE_B + 2 * AQ_TILE_B)   // 98304 B

__global__ void __launch_bounds__(256, 2) attn_hmma(
    const __nv_bfloat16* __restrict__ Qhi, const __nv_bfloat16* __restrict__ Qlo,
    const __nv_bfloat16* __restrict__ Khi, const __nv_bfloat16* __restrict__ Klo,
    const __nv_bfloat16* __restrict__ Vhi, const __nv_bfloat16* __restrict__ Vlo,
    uint32_t* __restrict__ Chi2, uint32_t* __restrict__ Clo2) {
    extern __shared__ __nv_bfloat16 smA[];
    const uint32_t sbase = smem_u32(smA);
    const uint32_t sQh_u = sbase + 2 * A_STAGE_B;
    const uint32_t sQl_u = sQh_u + AQ_TILE_B;

    const int tid  = threadIdx.x;
    const int wid  = tid >> 5;                 // 0..7, each 16 q-rows
    const int lane = tid & 31;
    const int grp  = lane >> 2, tg = lane & 3;
    const int qt = (int)gridDim.x - 1 - (int)blockIdx.x;   // heavy tiles first
    const int h  = blockIdx.y;
    const int b  = blockIdx.z;
    const int q0 = qt * 128;

    const int a_row = wid * 16 + ((lane >> 3) & 1) * 8 + (lane & 7);
    const int a_kby = (((lane >> 4) & 1) * 8) * 2;
    const int k_row4 = (lane >> 4) * 8 + (lane & 7);
    const int k_kby4 = (((lane >> 3) & 1) * 8) * 2;
    const int v_row4 = ((lane >> 3) & 1) * 8 + (lane & 7);
    const int v_cby4 = ((lane >> 4) * 8) * 2;

    // --- load Q tile (128 rows hi/lo) into dedicated smem (swizzled) ---
    #pragma unroll
    for (int t = 0; t < 4; t++) {
        int idx = tid + t * 256;               // 0..1023
        int r = idx >> 3, s = idx & 7;
        size_t g = (size_t)(b * SS + q0 + r) * DD + h * HD + s * 8;
        uint32_t so = SWZ(r * 128 + s * 16);
        *(uint4*)((char*)smA + 2 * A_STAGE_B + so) = *(const uint4*)(Qhi + g);
        *(uint4*)((char*)smA + 2 * A_STAGE_B + AQ_TILE_B + so) = *(const uint4*)(Qlo + g);
    }

    #define A_PREFETCH(stage, k0_)  do {                                              \
        uint32_t dstb = sbase + (uint32_t)(stage) * A_STAGE_B;                        \
        _Pragma("unroll")                                                             \
        for (int t = 0; t < 2; t++) {                                                 \
            int idx = tid + t * 256;                                                  \
            int r = idx >> 3, s = idx & 7;                                            \
            size_t g = (size_t)(b * SS + (k0_) + r) * DD + h * HD + s * 8;            \
            uint32_t so = SWZ(r * 128 + s * 16);                                      \
            CP16(dstb + so,                Khi + g);                                  \
            CP16(dstb + A_TILE_B + so,     Klo + g);                                  \
            CP16(dstb + 2*A_TILE_B + so,   Vhi + g);                                  \
            CP16(dstb + 3*A_TILE_B + so,   Vlo + g);                                  \
        }                                                                             \
        CP_COMMIT();                                                                  \
    } while (0)

    A_PREFETCH(0, 0);

    float m0 = -INFINITY, m1 = -INFINITY, l0 = 0.f, l1 = 0.f;
    float o[8][4];
    #pragma unroll
    for (int j = 0; j < 8; j++)
        #pragma unroll
        for (int e = 0; e < 4; e++) o[j][e] = 0.f;

    const int nkt = 2 * qt + 2;
    for (int kt = 0; kt < nkt; kt++) {
        const int k0 = kt * 64;
        CP_WAIT0();
        __syncthreads();
        if (kt + 1 < nkt) A_PREFETCH((kt + 1) & 1, (kt + 1) * 64);

        const uint32_t sb = sbase + (uint32_t)(kt & 1) * A_STAGE_B;
        const uint32_t sKh_u = sb, sKl_u = sb + A_TILE_B;
        const uint32_t sVh_u = sb + 2 * A_TILE_B, sVl_u = sb + 3 * A_TILE_B;

        // --- S = Q K^T ---
        float sc[8][4];
        #pragma unroll
        for (int j = 0; j < 8; j++)
            #pragma unroll
            for (int e = 0; e < 4; e++) sc[j][e] = 0.f;

        #pragma unroll
        for (int ks = 0; ks < 4; ks++) {
            uint32_t qh[4], ql[4];
            {
                uint32_t off = SWZ(a_row * 128 + ks * 32 + a_kby);
                ldmatrix_x4(qh[0], qh[1], qh[2], qh[3], sQh_u + off);
                ldmatrix_x4(ql[0], ql[1], ql[2], ql[3], sQl_u + off);
            }
            uint32_t kb[8][2], kl[8][2];
            #pragma unroll
            for (int j2 = 0; j2 < 8; j2 += 2) {
                uint32_t off = SWZ((j2 * 8 + k_row4) * 128 + ks * 32 + k_kby4);
                ldmatrix_x4(kb[j2][0], kb[j2][1], kb[j2+1][0], kb[j2+1][1], sKh_u + off);
                ldmatrix_x4(kl[j2][0], kl[j2][1], kl[j2+1][0], kl[j2+1][1], sKl_u + off);
            }
            #pragma unroll
            for (int j = 0; j < 8; j++) mma_bf16(sc[j], qh, kb[j]);
            #pragma unroll
            for (int j = 0; j < 8; j++) mma_bf16(sc[j], qh, kl[j]);
            #pragma unroll
            for (int j = 0; j < 8; j++) mma_bf16(sc[j], ql, kb[j]);
        }

        // --- causal mask (global compare; only last two k-tiles) ---
        if (kt >= 2 * qt) {
            const int qg0 = q0 + wid * 16 + grp;
            #pragma unroll
            for (int j = 0; j < 8; j++) {
                int kg = k0 + j * 8 + 2 * tg;
                if (kg     > qg0)     sc[j][0] = -INFINITY;
                if (kg + 1 > qg0)     sc[j][1] = -INFINITY;
                if (kg     > qg0 + 8) sc[j][2] = -INFINITY;
                if (kg + 1 > qg0 + 8) sc[j][3] = -INFINITY;
            }
        }

        // --- online softmax in exp2 domain, raw ex2.approx ---
        float mx0 = -INFINITY, mx1 = -INFINITY;
        #pragma unroll
        for (int j = 0; j < 8; j++) {
            mx0 = fmaxf(mx0, fmaxf(sc[j][0], sc[j][1]));
            mx1 = fmaxf(mx1, fmaxf(sc[j][2], sc[j][3]));
        }
        mx0 = fmaxf(mx0, __shfl_xor_sync(0xffffffffu, mx0, 1));
        mx0 = fmaxf(mx0, __shfl_xor_sync(0xffffffffu, mx0, 2));
        mx1 = fmaxf(mx1, __shfl_xor_sync(0xffffffffu, mx1, 1));
        mx1 = fmaxf(mx1, __shfl_xor_sync(0xffffffffu, mx1, 2));
        float mn0 = fmaxf(m0, mx0), mn1 = fmaxf(m1, mx1);
        float al0 = ex2(m0 - mn0), al1 = ex2(m1 - mn1);
        float s0 = 0.f, s1 = 0.f;
        #pragma unroll
        for (int j = 0; j < 8; j++) {
            sc[j][0] = ex2(sc[j][0] - mn0);
            sc[j][1] = ex2(sc[j][1] - mn0);
            sc[j][2] = ex2(sc[j][2] - mn1);
            sc[j][3] = ex2(sc[j][3] - mn1);
            s0 += sc[j][0] + sc[j][1];
            s1 += sc[j][2] + sc[j][3];
        }
        s0 += __shfl_xor_sync(0xffffffffu, s0, 1);
        s0 += __shfl_xor_sync(0xffffffffu, s0, 2);
        s1 += __shfl_xor_sync(0xffffffffu, s1, 1);
        s1 += __shfl_xor_sync(0xffffffffu, s1, 2);
        l0 = l0 * al0 + s0;  m0 = mn0;
        l1 = l1 * al1 + s1;  m1 = mn1;
        #pragma unroll
        for (int j = 0; j < 8; j++) {
            o[j][0] *= al0; o[j][1] *= al0;
            o[j][2] *= al1; o[j][3] *= al1;
        }

        // --- O += P V ---
        #pragma unroll
        for (int ks = 0; ks < 4; ks++) {
            uint32_t ph[4], pl[4];
            split2(sc[2*ks][0],   sc[2*ks][1],   ph[0], pl[0]);
            split2(sc[2*ks][2],   sc[2*ks][3],   ph[1], pl[1]);
            split2(sc[2*ks+1][0], sc[2*ks+1][1], ph[2], pl[2]);
            split2(sc[2*ks+1][2], sc[2*ks+1][3], ph[3], pl[3]);
            uint32_t vb[8][2], vl[8][2];
            #pragma unroll
            for (int j2 = 0; j2 < 8; j2 += 2) {
                uint32_t off = SWZ((ks * 16 + v_row4) * 128 + j2 * 16 + v_cby4);
                ldmatrix_x4_trans(vb[j2][0], vb[j2][1], vb[j2+1][0], vb[j2+1][1], sVh_u + off);
                ldmatrix_x4_trans(vl[j2][0], vl[j2][1], vl[j2+1][0], vl[j2+1][1], sVl_u + off);
            }
            #pragma unroll
            for (int j2 = 0; j2 < 8; j2++) mma_bf16(o[j2], ph, vb[j2]);
            #pragma unroll
            for (int j2 = 0; j2 < 8; j2++) mma_bf16(o[j2], ph, vl[j2]);
            #pragma unroll
            for (int j2 = 0; j2 < 8; j2++) mma_bf16(o[j2], pl, vb[j2]);
        }
    }

    // --- epilogue: ctx = O / l, written as bf16 hi/lo pairs ---
    const float inv0 = 1.f / l0, inv1 = 1.f / l1;
    const int row0 = b * SS + q0 + wid * 16 + grp;
    #pragma unroll
    for (int j2 = 0; j2 < 8; j2++) {
        const int cidx = h * 32 + j2 * 4 + tg;    // bf162 units
        uint32_t h2, l2;
        split2(o[j2][0] * inv0, o[j2][1] * inv0, h2, l2);
        Chi2[(size_t)row0 * (DD / 2) + cidx] = h2;
        Clo2[(size_t)row0 * (DD / 2) + cidx] = l2;
        split2(o[j2][2] * inv1, o[j2][3] * inv1, h2, l2);
        Chi2[(size_t)(row0 + 8) * (DD / 2) + cidx] = h2;
        Clo2[(size_t)(row0 + 8) * (DD / 2) + cidx] = l2;
    }
    #undef A_PREFETCH
}

// ---------------------------------------------------------------------------
extern "C" void kernel_launch(void* const* d_in, const int* in_sizes, int n_in,
                              void* d_out, int out_size) {
    const float* x  = (const float*)d_in[0];
    const float* Wq = (const float*)d_in[1];
    const float* bq = (const float*)d_in[2];
    const float* Wk = (const float*)d_in[3];
    const float* bk = (const float*)d_in[4];
    const float* Wv = (const float*)d_in[5];
    const float* bv = (const float*)d_in[6];
    const float* Wo = (const float*)d_in[7];
    const float* bo = (const float*)d_in[8];
    float* out = (float*)d_out;

    __nv_bfloat16 *xhi, *xlo, *chi, *clo;
    cudaGetSymbolAddress((void**)&xhi, g_xhi);
    cudaGetSymbolAddress((void**)&xlo, g_xlo);
    cudaGetSymbolAddress((void**)&chi, g_chi);
    cudaGetSymbolAddress((void**)&clo, g_clo);
    __nv_bfloat16 *qhi, *qlo, *khi, *klo, *vhi, *vlo;
    cudaGetSymbolAddress((void**)&qhi, g_qhi);
    cudaGetSymbolAddress((void**)&qlo, g_qlo);
    cudaGetSymbolAddress((void**)&khi, g_khi);
    cudaGetSymbolAddress((void**)&klo, g_klo);
    cudaGetSymbolAddress((void**)&vhi, g_vhi);
    cudaGetSymbolAddress((void**)&vlo, g_vlo);
    __nv_bfloat16 *wqh, *wql, *wkh, *wkl, *wvh, *wvl, *woh, *wol;
    cudaGetSymbolAddress((void**)&wqh, g_wq_hi);
    cudaGetSymbolAddress((void**)&wql, g_wq_lo);
    cudaGetSymbolAddress((void**)&wkh, g_wk_hi);
    cudaGetSymbolAddress((void**)&wkl, g_wk_lo);
    cudaGetSymbolAddress((void**)&wvh, g_wv_hi);
    cudaGetSymbolAddress((void**)&wvl, g_wv_lo);
    cudaGetSymbolAddress((void**)&woh, g_wo_hi);
    cudaGetSymbolAddress((void**)&wol, g_wo_lo);

    // 1) input conversions (x split + all 4 weights in one launch)
    int n4 = M_TOT * DD / 4;
    cvt_split4<<<(n4 + 255) / 256, 256>>>((const float4*)x,
                                          (__nv_bfloat162*)xhi, (__nv_bfloat162*)xlo, n4);
    WJob jq{Wq, wqh, wql}, jk{Wk, wkh, wkl}, jv{Wv, wvh, wvl}, jo{Wo, woh, wol};
    cvt_wT4<<<dim3(DD / 32, DD / 32, 4), dim3(32, 8)>>>(jq, jk, jv, jo);

    // 2) fused QKV projection (one launch; Q pre-scaled by 0.125*log2(e))
    cudaFuncSetAttribute(gemm_qkv, cudaFuncAttributeMaxDynamicSharedMemorySize, SMEM_GEMM);
    cudaFuncSetAttribute(gemm_hmma, cudaFuncAttributeMaxDynamicSharedMemorySize, SMEM_GEMM);
    QKVJob job;
    job.bhi[0] = wqh; job.blo[0] = wql; job.bias[0] = bq;
    job.chi[0] = (uint32_t*)qhi; job.clo[0] = (uint32_t*)qlo;
    job.scale[0] = 0.125f * 1.44269504f;
    job.bhi[1] = wkh; job.blo[1] = wkl; job.bias[1] = bk;
    job.chi[1] = (uint32_t*)khi; job.clo[1] = (uint32_t*)klo;
    job.scale[1] = 1.0f;
    job.bhi[2] = wvh; job.blo[2] = wvl; job.bias[2] = bv;
    job.chi[2] = (uint32_t*)vhi; job.clo[2] = (uint32_t*)vlo;
    job.scale[2] = 1.0f;
    dim3 gq(3 * DD / CTA_N, M_TOT / CTA_M);   // (24, 32) = 768 CTAs
    gemm_qkv<<<gq, 256, SMEM_GEMM>>>(xhi, xlo, job, M_TOT, DD, DD);

    // 3) attention on tensor cores -> ctx bf16 hi/lo (256 thr, q-tile 128)
    cudaFuncSetAttribute(attn_hmma, cudaFuncAttributeMaxDynamicSharedMemorySize, SMEM_ATTN);
    attn_hmma<<<dim3(SS / 128, HH, BB), 256, SMEM_ATTN>>>(
        qhi, qlo, khi, klo, vhi, vlo, (uint32_t*)chi, (uint32_t*)clo);

    // 4) output projection -> fp32 out
    dim3 gg(DD / CTA_N, M_TOT / CTA_M);
    gemm_hmma<<<gg, 256, SMEM_GEMM>>>(chi, clo, woh, wol, bo, out, M_TOT, DD, DD);
}

// round 14
// speedup vs baseline: 1.4424x; 1.4424x over previous
#include <cuda_runtime.h>
#include <cuda_fp16.h>
#include <cstdint>
#include <math.h>

#define BB 2
#define SS 2048
#define DD 1024
#define HH 16
#define HD 64
#define M_TOT (BB*SS)   // 4096

// ---------------------------------------------------------------------------
// Scratch (__device__ globals: allocation-free per harness rules)
// A-side operands are split (hi/lo); B-side operands are plain fp16.
// ---------------------------------------------------------------------------
__device__ __half g_xhi[M_TOT * DD];
__device__ __half g_xlo[M_TOT * DD];
__device__ __half g_chi[M_TOT * DD];
__device__ __half g_clo[M_TOT * DD];

__device__ __half g_qhi[M_TOT * DD];
__device__ __half g_qlo[M_TOT * DD];
__device__ __half g_kh[M_TOT * DD];
__device__ __half g_vh[M_TOT * DD];

__device__ __half g_wqT[DD * DD];
__device__ __half g_wkT[DD * DD];
__device__ __half g_wvT[DD * DD];
__device__ __half g_woT[DD * DD];

// ---------------------------------------------------------------------------
// helpers
// ---------------------------------------------------------------------------
__device__ __forceinline__ uint32_t smem_u32(const void* p) {
    uint32_t a;
    asm("{ .reg .u64 t; cvta.to.shared.u64 t, %1; cvt.u32.u64 %0, t; }" : "=r"(a) : "l"(p));
    return a;
}
__device__ __forceinline__ void ldmatrix_x4(uint32_t& r0, uint32_t& r1, uint32_t& r2,
                                            uint32_t& r3, uint32_t addr) {
    asm volatile("ldmatrix.sync.aligned.m8n8.x4.shared.b16 {%0,%1,%2,%3}, [%4];"
                 : "=r"(r0), "=r"(r1), "=r"(r2), "=r"(r3) : "r"(addr));
}
__device__ __forceinline__ void ldmatrix_x4_trans(uint32_t& r0, uint32_t& r1, uint32_t& r2,
                                                  uint32_t& r3, uint32_t addr) {
    asm volatile("ldmatrix.sync.aligned.m8n8.x4.trans.shared.b16 {%0,%1,%2,%3}, [%4];"
                 : "=r"(r0), "=r"(r1), "=r"(r2), "=r"(r3) : "r"(addr));
}
__device__ __forceinline__ void mma_f16(float* d, const uint32_t* a, const uint32_t* b) {
    asm volatile(
        "mma.sync.aligned.m16n8k16.row.col.f32.f16.f16.f32 "
        "{%0,%1,%2,%3}, {%4,%5,%6,%7}, {%8,%9}, {%0,%1,%2,%3};"
        : "+f"(d[0]), "+f"(d[1]), "+f"(d[2]), "+f"(d[3])
        : "r"(a[0]), "r"(a[1]), "r"(a[2]), "r"(a[3]), "r"(b[0]), "r"(b[1]));
}
// fast raw exp2 (args <= 0, bounded; -inf -> 0)
__device__ __forceinline__ float ex2(float x) {
    float r;
    asm("ex2.approx.ftz.f32 %0, %1;" : "=f"(r) : "f"(x));
    return r;
}
// fp16 split: pack (x,y) into f16x2 hi-pair + residual lo-pair (A exact to 2^-24)
__device__ __forceinline__ void split2h(float x, float y, uint32_t& hi, uint32_t& lo) {
    __half2 h = __floats2half2_rn(x, y);
    float2 f = __half22float2(h);
    __half2 l = __floats2half2_rn(x - f.x, y - f.y);
    hi = *reinterpret_cast<uint32_t*>(&h);
    lo = *reinterpret_cast<uint32_t*>(&l);
}
__device__ __forceinline__ uint32_t pack_h2(float x, float y) {
    __half2 h = __floats2half2_rn(x, y);
    return *reinterpret_cast<uint32_t*>(&h);
}
#define CP16(d, s) asm volatile("cp.async.cg.shared.global [%0], [%1], 16;" :: "r"(d), "l"(s))
#define CP_COMMIT() asm volatile("cp.async.commit_group;" ::: "memory")
#define CP_WAIT0()  asm volatile("cp.async.wait_group 0;" ::: "memory")
// SW128 swizzle (1024B atoms)
#define SWZ(b) ((uint32_t)(b) ^ ((((uint32_t)(b)) >> 3) & 0x70u))

// ---------------------------------------------------------------------------
// fp32 -> fp16 hi/lo split (elementwise, vectorized)
// ---------------------------------------------------------------------------
__global__ void cvt_split4(const float4* __restrict__ in,
                           uint32_t* __restrict__ hi,
                           uint32_t* __restrict__ lo, int n4) {
    int i = blockIdx.x * blockDim.x + threadIdx.x;
    if (i >= n4) return;
    float4 v = in[i];
    uint32_t h0, l0, h1, l1;
    split2h(v.x, v.y, h0, l0);
    split2h(v.z, v.w, h1, l1);
    hi[2*i]   = h0;
    hi[2*i+1] = h1;
    lo[2*i]   = l0;
    lo[2*i+1] = l1;
}

// ---------------------------------------------------------------------------
// W[K][N] fp32 -> transposed plain fp16 [N][K]; 4 weights in one launch
// ---------------------------------------------------------------------------
struct WJob { const float* W; __half* hT; };

__global__ void cvt_wT4(WJob j0, WJob j1, WJob j2, WJob j3) {
    __shared__ float t[32][33];
    WJob j = (blockIdx.z == 0) ? j0 : (blockIdx.z == 1) ? j1 : (blockIdx.z == 2) ? j2 : j3;
    int n0 = blockIdx.x * 32, k0 = blockIdx.y * 32;
    int tx = threadIdx.x, ty = threadIdx.y;
    #pragma unroll
    for (int r = 0; r < 32; r += 8)
        t[ty + r][tx] = j.W[(size_t)(k0 + ty + r) * DD + n0 + tx];
    __syncthreads();
    #pragma unroll
    for (int r = 0; r < 32; r += 8) {
        float v = t[tx][ty + r];
        j.hT[(size_t)(n0 + ty + r) * DD + k0 + tx] = __float2half_rn(v);
    }
}

// ---------------------------------------------------------------------------
// GEMM geometry: A hi/lo + B plain = 3 tiles/stage
// ---------------------------------------------------------------------------
#define CTA_M 128
#define CTA_N 128
#define KC 32
#define LDT 40
#define G_TILE_B (128 * LDT * 2)           // 10240 B
#define G_STAGE_B (3 * G_TILE_B)           // 30720 B
#define SMEM_GEMM (2 * G_STAGE_B)          // 61440 B

// ---------------------------------------------------------------------------
// Fused QKV GEMM: one launch, proj = blockIdx.x / 8.
// Q (proj 0) -> split hi/lo; K/V (proj 1,2) -> plain fp16.
// ---------------------------------------------------------------------------
struct QKVJob {
    const __half* bT[3];
    const float*  bias[3];
    uint32_t*     chi[3];
    uint32_t*     clo[3];   // null -> plain fp16 output
    float         scale[3];
};

__global__ void __launch_bounds__(256, 2) gemm_qkv(
    const __half* __restrict__ Ahi, const __half* __restrict__ Alo,
    QKVJob job, int M, int N, int K) {
    extern __shared__ __half smG[];
    const uint32_t sbase = smem_u32(smG);

    const int proj = blockIdx.x >> 3;
    const __half* __restrict__ BT = job.bT[proj];
    const float* __restrict__ bias = job.bias[proj];
    uint32_t* __restrict__ Chi2 = job.chi[proj];
    uint32_t* __restrict__ Clo2 = job.clo[proj];
    const float scale = job.scale[proj];

    const int tid  = threadIdx.x;
    const int wid  = tid >> 5;
    const int lane = tid & 31;
    const int warp_m = wid & 1;
    const int warp_n = wid >> 1;
    const int m0 = blockIdx.y * CTA_M;
    const int n0 = (blockIdx.x & 7) * CTA_N;

    float acc[4][4][4];
    #pragma unroll
    for (int i = 0; i < 4; i++)
        #pragma unroll
        for (int j = 0; j < 4; j++)
            #pragma unroll
            for (int e = 0; e < 4; e++) acc[i][j][e] = 0.f;

    const int lm_r  = lane & 7;
    const int lm_m4 = lane >> 3;
    const int a_row = warp_m * 64 + (lm_m4 & 1) * 8 + lm_r;
    const int a_kof = (lm_m4 >> 1) * 8;
    const int b_row4 = warp_n * 32 + (lane >> 4) * 8 + lm_r;
    const int b_kof4 = ((lane >> 3) & 1) * 8;

    const int ld_row = tid >> 2, ld_s = tid & 3;
    const int nchunks = K / KC;

    #define G_PREFETCH(stage, k0_)  do {                                              \
        uint32_t dstb = sbase + (uint32_t)(stage) * G_STAGE_B;                        \
        _Pragma("unroll")                                                             \
        for (int t = 0; t < 2; t++) {                                                 \
            int row = ld_row + t * 64;                                                \
            uint32_t so = (uint32_t)(row * LDT + ld_s * 8) * 2;                       \
            CP16(dstb + so,               Ahi + (size_t)(m0 + row) * K + (k0_) + ld_s * 8); \
            CP16(dstb + G_TILE_B + so,    Alo + (size_t)(m0 + row) * K + (k0_) + ld_s * 8); \
            CP16(dstb + 2*G_TILE_B + so,  BT  + (size_t)(n0 + row) * K + (k0_) + ld_s * 8); \
        }                                                                             \
        CP_COMMIT();                                                                  \
    } while (0)

    G_PREFETCH(0, 0);

    for (int c = 0; c < nchunks; c++) {
        CP_WAIT0();
        __syncthreads();
        if (c + 1 < nchunks) G_PREFETCH((c + 1) & 1, (c + 1) * KC);

        const uint32_t sb = sbase + (uint32_t)(c & 1) * G_STAGE_B;
        const uint32_t sAhi = sb, sAlo = sb + G_TILE_B, sB = sb + 2 * G_TILE_B;

        #pragma unroll
        for (int ks = 0; ks < 2; ks++) {
            uint32_t ahi[4][4], alo[4][4], bh[4][2];
            #pragma unroll
            for (int i = 0; i < 4; i++) {
                uint32_t off = (uint32_t)((a_row + i * 16) * LDT + ks * 16 + a_kof) * 2;
                ldmatrix_x4(ahi[i][0], ahi[i][1], ahi[i][2], ahi[i][3], sAhi + off);
                ldmatrix_x4(alo[i][0], alo[i][1], alo[i][2], alo[i][3], sAlo + off);
            }
            #pragma unroll
            for (int j2 = 0; j2 < 4; j2 += 2) {
                uint32_t off = (uint32_t)((b_row4 + j2 * 8) * LDT + ks * 16 + b_kof4) * 2;
                ldmatrix_x4(bh[j2][0], bh[j2][1], bh[j2+1][0], bh[j2+1][1], sB + off);
            }
            #pragma unroll
            for (int i = 0; i < 4; i++)
                #pragma unroll
                for (int j = 0; j < 4; j++) {
                    mma_f16(acc[i][j], ahi[i], bh[j]);
                    mma_f16(acc[i][j], alo[i], bh[j]);
                }
        }
    }

    __syncthreads();
    const int grp = lane >> 2, tg = lane & 3;
    #pragma unroll
    for (int i = 0; i < 4; i++) {
        int row0 = m0 + warp_m * 64 + i * 16 + grp;
        #pragma unroll
        for (int j = 0; j < 4; j++) {
            int col = n0 + warp_n * 32 + j * 8 + tg * 2;
            float b0 = bias[col], b1 = bias[col + 1];
            float v0 = (acc[i][j][0] + b0) * scale, v1 = (acc[i][j][1] + b1) * scale;
            float v2 = (acc[i][j][2] + b0) * scale, v3 = (acc[i][j][3] + b1) * scale;
            if (Clo2) {
                uint32_t h2, l2;
                split2h(v0, v1, h2, l2);
                Chi2[(size_t)row0 * (N / 2) + col / 2] = h2;
                Clo2[(size_t)row0 * (N / 2) + col / 2] = l2;
                split2h(v2, v3, h2, l2);
                Chi2[(size_t)(row0 + 8) * (N / 2) + col / 2] = h2;
                Clo2[(size_t)(row0 + 8) * (N / 2) + col / 2] = l2;
            } else {
                Chi2[(size_t)row0 * (N / 2) + col / 2] = pack_h2(v0, v1);
                Chi2[(size_t)(row0 + 8) * (N / 2) + col / 2] = pack_h2(v2, v3);
            }
        }
    }
    #undef G_PREFETCH
}

// ---------------------------------------------------------------------------
// Out-projection GEMM: ctx hi/lo @ WoT plain -> fp32 out
// ---------------------------------------------------------------------------
__global__ void __launch_bounds__(256, 2) gemm_hmma(
    const __half* __restrict__ Ahi, const __half* __restrict__ Alo,
    const __half* __restrict__ BT, const float* __restrict__ bias,
    float* __restrict__ Cf, int M, int N, int K) {
    extern __shared__ __half smG[];
    const uint32_t sbase = smem_u32(smG);

    const int tid  = threadIdx.x;
    const int wid  = tid >> 5;
    const int lane = tid & 31;
    const int warp_m = wid & 1;
    const int warp_n = wid >> 1;
    const int m0 = blockIdx.y * CTA_M;
    const int n0 = blockIdx.x * CTA_N;

    float acc[4][4][4];
    #pragma unroll
    for (int i = 0; i < 4; i++)
        #pragma unroll
        for (int j = 0; j < 4; j++)
            #pragma unroll
            for (int e = 0; e < 4; e++) acc[i][j][e] = 0.f;

    const int lm_r  = lane & 7;
    const int lm_m4 = lane >> 3;
    const int a_row = warp_m * 64 + (lm_m4 & 1) * 8 + lm_r;
    const int a_kof = (lm_m4 >> 1) * 8;
    const int b_row4 = warp_n * 32 + (lane >> 4) * 8 + lm_r;
    const int b_kof4 = ((lane >> 3) & 1) * 8;

    const int ld_row = tid >> 2, ld_s = tid & 3;
    const int nchunks = K / KC;

    #define G_PREFETCH(stage, k0_)  do {                                              \
        uint32_t dstb = sbase + (uint32_t)(stage) * G_STAGE_B;                        \
        _Pragma("unroll")                                                             \
        for (int t = 0; t < 2; t++) {                                                 \
            int row = ld_row + t * 64;                                                \
            uint32_t so = (uint32_t)(row * LDT + ld_s * 8) * 2;                       \
            CP16(dstb + so,               Ahi + (size_t)(m0 + row) * K + (k0_) + ld_s * 8); \
            CP16(dstb + G_TILE_B + so,    Alo + (size_t)(m0 + row) * K + (k0_) + ld_s * 8); \
            CP16(dstb + 2*G_TILE_B + so,  BT  + (size_t)(n0 + row) * K + (k0_) + ld_s * 8); \
        }                                                                             \
        CP_COMMIT();                                                                  \
    } while (0)

    G_PREFETCH(0, 0);

    for (int c = 0; c < nchunks; c++) {
        CP_WAIT0();
        __syncthreads();
        if (c + 1 < nchunks) G_PREFETCH((c + 1) & 1, (c + 1) * KC);

        const uint32_t sb = sbase + (uint32_t)(c & 1) * G_STAGE_B;
        const uint32_t sAhi = sb, sAlo = sb + G_TILE_B, sB = sb + 2 * G_TILE_B;

        #pragma unroll
        for (int ks = 0; ks < 2; ks++) {
            uint32_t ahi[4][4], alo[4][4], bh[4][2];
            #pragma unroll
            for (int i = 0; i < 4; i++) {
                uint32_t off = (uint32_t)((a_row + i * 16) * LDT + ks * 16 + a_kof) * 2;
                ldmatrix_x4(ahi[i][0], ahi[i][1], ahi[i][2], ahi[i][3], sAhi + off);
                ldmatrix_x4(alo[i][0], alo[i][1], alo[i][2], alo[i][3], sAlo + off);
            }
            #pragma unroll
            for (int j2 = 0; j2 < 4; j2 += 2) {
                uint32_t off = (uint32_t)((b_row4 + j2 * 8) * LDT + ks * 16 + b_kof4) * 2;
                ldmatrix_x4(bh[j2][0], bh[j2][1], bh[j2+1][0], bh[j2+1][1], sB + off);
            }
            #pragma unroll
            for (int i = 0; i < 4; i++)
                #pragma unroll
                for (int j = 0; j < 4; j++) {
                    mma_f16(acc[i][j], ahi[i], bh[j]);
                    mma_f16(acc[i][j], alo[i], bh[j]);
                }
        }
    }

    __syncthreads();
    const int grp = lane >> 2, tg = lane & 3;
    #pragma unroll
    for (int i = 0; i < 4; i++) {
        int row0 = m0 + warp_m * 64 + i * 16 + grp;
        #pragma unroll
        for (int j = 0; j < 4; j++) {
            int col = n0 + warp_n * 32 + j * 8 + tg * 2;
            float b0 = bias[col], b1 = bias[col + 1];
            float* p0 = Cf + (size_t)row0 * N + col;
            p0[0] = acc[i][j][0] + b0;
            p0[1] = acc[i][j][1] + b1;
            float* p1 = Cf + (size_t)(row0 + 8) * N + col;
            p1[0] = acc[i][j][2] + b0;
            p1[1] = acc[i][j][3] + b1;
        }
    }
    #undef G_PREFETCH
}

// ---------------------------------------------------------------------------
// fp16 HMMA causal flash attention, v8: Q split (frags in regs), K/V plain.
// Stage = Kh + Vh = 16 KB; 2 stages = 32 KB -> 3 CTAs/SM.
// Q pre-scaled by 0.125*log2(e).
// ---------------------------------------------------------------------------
#define A_TILE_B 8192                      // 64 rows * 128 B
#define A_STAGE_B (2 * A_TILE_B)           // 16384 B (K + V)
#define SMEM_ATTN (2 * A_STAGE_B)          // 32768 B

__global__ void __launch_bounds__(128, 3) attn_hmma(
    const __half* __restrict__ Qhi, const __half* __restrict__ Qlo,
    const __half* __restrict__ Kh, const __half* __restrict__ Vh,
    uint32_t* __restrict__ Chi2, uint32_t* __restrict__ Clo2) {
    extern __shared__ __half smA[];
    const uint32_t sbase = smem_u32(smA);

    const int tid  = threadIdx.x;
    const int wid  = tid >> 5;
    const int lane = tid & 31;
    const int grp  = lane >> 2, tg = lane & 3;
    const int qt = (int)gridDim.x - 1 - (int)blockIdx.x;   // heavy tiles first
    const int h  = blockIdx.y;
    const int b  = blockIdx.z;
    const int q0 = qt * 64;

    const int a_row = wid * 16 + ((lane >> 3) & 1) * 8 + (lane & 7);
    const int a_kby = (((lane >> 4) & 1) * 8) * 2;
    const int k_row4 = (lane >> 4) * 8 + (lane & 7);
    const int k_kby4 = (((lane >> 3) & 1) * 8) * 2;
    const int v_row4 = ((lane >> 3) & 1) * 8 + (lane & 7);
    const int v_cby4 = ((lane >> 4) * 8) * 2;

    // --- stage Q hi/lo through stage area (swizzled), preload frags ---
    #pragma unroll
    for (int t = 0; t < 4; t++) {
        int idx = tid + t * 128;
        int r = idx >> 3, s = idx & 7;
        size_t g = (size_t)(b * SS + q0 + r) * DD + h * HD + s * 8;
        uint32_t so = SWZ(r * 128 + s * 16);
        *(uint4*)((char*)smA + so) = *(const uint4*)(Qhi + g);
        *(uint4*)((char*)smA + A_TILE_B + so) = *(const uint4*)(Qlo + g);
    }
    __syncthreads();
    uint32_t qh[4][4], ql[4][4];
    #pragma unroll
    for (int ks = 0; ks < 4; ks++) {
        uint32_t off = SWZ(a_row * 128 + ks * 32 + a_kby);
        ldmatrix_x4(qh[ks][0], qh[ks][1], qh[ks][2], qh[ks][3], sbase + off);
        ldmatrix_x4(ql[ks][0], ql[ks][1], ql[ks][2], ql[ks][3], sbase + A_TILE_B + off);
    }
    __syncthreads();

    #define A_PREFETCH(stage, k0_)  do {                                              \
        uint32_t dstb = sbase + (uint32_t)(stage) * A_STAGE_B;                        \
        _Pragma("unroll")                                                             \
        for (int t = 0; t < 4; t++) {                                                 \
            int idx = tid + t * 128;                                                  \
            int r = idx >> 3, s = idx & 7;                                            \
            size_t g = (size_t)(b * SS + (k0_) + r) * DD + h * HD + s * 8;            \
            uint32_t so = SWZ(r * 128 + s * 16);                                      \
            CP16(dstb + so,              Kh + g);                                     \
            CP16(dstb + A_TILE_B + so,   Vh + g);                                     \
        }                                                                             \
        CP_COMMIT();                                                                  \
    } while (0)

    A_PREFETCH(0, 0);

    float m0 = -INFINITY, m1 = -INFINITY, l0 = 0.f, l1 = 0.f;
    float o[8][4];
    #pragma unroll
    for (int j = 0; j < 8; j++)
        #pragma unroll
        for (int e = 0; e < 4; e++) o[j][e] = 0.f;

    for (int kt = 0; kt <= qt; kt++) {
        CP_WAIT0();
        __syncthreads();
        if (kt < qt) A_PREFETCH((kt + 1) & 1, (kt + 1) * 64);

        const uint32_t sb = sbase + (uint32_t)(kt & 1) * A_STAGE_B;
        const uint32_t sKh_u = sb, sVh_u = sb + A_TILE_B;

        // --- S = Q K^T (2-term: Qh*K + Ql*K) ---
        float sc[8][4];
        #pragma unroll
        for (int j = 0; j < 8; j++)
            #pragma unroll
            for (int e = 0; e < 4; e++) sc[j][e] = 0.f;

        #pragma unroll
        for (int ks = 0; ks < 4; ks++) {
            uint32_t kb[8][2];
            #pragma unroll
            for (int j2 = 0; j2 < 8; j2 += 2) {
                uint32_t off = SWZ((j2 * 8 + k_row4) * 128 + ks * 32 + k_kby4);
                ldmatrix_x4(kb[j2][0], kb[j2][1], kb[j2+1][0], kb[j2+1][1], sKh_u + off);
            }
            #pragma unroll
            for (int j = 0; j < 8; j++) mma_f16(sc[j], qh[ks], kb[j]);
            #pragma unroll
            for (int j = 0; j < 8; j++) mma_f16(sc[j], ql[ks], kb[j]);
        }

        // --- causal mask on diagonal tile ---
        if (kt == qt) {
            const int qr0 = wid * 16 + grp;
            #pragma unroll
            for (int j = 0; j < 8; j++) {
                int kc = j * 8 + 2 * tg;
                if (kc     > qr0)     sc[j][0] = -INFINITY;
                if (kc + 1 > qr0)     sc[j][1] = -INFINITY;
                if (kc     > qr0 + 8) sc[j][2] = -INFINITY;
                if (kc + 1 > qr0 + 8) sc[j][3] = -INFINITY;
            }
        }

        // --- online softmax in exp2 domain, raw ex2.approx ---
        float mx0 = -INFINITY, mx1 = -INFINITY;
        #pragma unroll
        for (int j = 0; j < 8; j++) {
            mx0 = fmaxf(mx0, fmaxf(sc[j][0], sc[j][1]));
            mx1 = fmaxf(mx1, fmaxf(sc[j][2], sc[j][3]));
        }
        mx0 = fmaxf(mx0, __shfl_xor_sync(0xffffffffu, mx0, 1));
        mx0 = fmaxf(mx0, __shfl_xor_sync(0xffffffffu, mx0, 2));
        mx1 = fmaxf(mx1, __shfl_xor_sync(0xffffffffu, mx1, 1));
        mx1 = fmaxf(mx1, __shfl_xor_sync(0xffffffffu, mx1, 2));
        float mn0 = fmaxf(m0, mx0), mn1 = fmaxf(m1, mx1);
        float al0 = ex2(m0 - mn0), al1 = ex2(m1 - mn1);
        float s0 = 0.f, s1 = 0.f;
        #pragma unroll
        for (int j = 0; j < 8; j++) {
            sc[j][0] = ex2(sc[j][0] - mn0);
            sc[j][1] = ex2(sc[j][1] - mn0);
            sc[j][2] = ex2(sc[j][2] - mn1);
            sc[j][3] = ex2(sc[j][3] - mn1);
            s0 += sc[j][0] + sc[j][1];
            s1 += sc[j][2] + sc[j][3];
        }
        s0 += __shfl_xor_sync(0xffffffffu, s0, 1);
        s0 += __shfl_xor_sync(0xffffffffu, s0, 2);
        s1 += __shfl_xor_sync(0xffffffffu, s1, 1);
        s1 += __shfl_xor_sync(0xffffffffu, s1, 2);
        l0 = l0 * al0 + s0;  m0 = mn0;
        l1 = l1 * al1 + s1;  m1 = mn1;
        #pragma unroll
        for (int j = 0; j < 8; j++) {
            o[j][0] *= al0; o[j][1] *= al0;
            o[j][2] *= al1; o[j][3] *= al1;
        }

        // --- O += P V (2-term: Ph*V + Pl*V) ---
        #pragma unroll
        for (int ks = 0; ks < 4; ks++) {
            uint32_t ph[4], pl[4];
            split2h(sc[2*ks][0],   sc[2*ks][1],   ph[0], pl[0]);
            split2h(sc[2*ks][2],   sc[2*ks][3],   ph[1], pl[1]);
            split2h(sc[2*ks+1][0], sc[2*ks+1][1], ph[2], pl[2]);
            split2h(sc[2*ks+1][2], sc[2*ks+1][3], ph[3], pl[3]);
            uint32_t vb[8][2];
            #pragma unroll
            for (int j2 = 0; j2 < 8; j2 += 2) {
                uint32_t off = SWZ((ks * 16 + v_row4) * 128 + j2 * 16 + v_cby4);
                ldmatrix_x4_trans(vb[j2][0], vb[j2][1], vb[j2+1][0], vb[j2+1][1], sVh_u + off);
            }
            #pragma unroll
            for (int j2 = 0; j2 < 8; j2++) mma_f16(o[j2], ph, vb[j2]);
            #pragma unroll
            for (int j2 = 0; j2 < 8; j2++) mma_f16(o[j2], pl, vb[j2]);
        }
    }

    // --- epilogue: ctx = O / l, written as fp16 hi/lo pairs ---
    const float inv0 = 1.f / l0, inv1 = 1.f / l1;
    const int row0 = b * SS + q0 + wid * 16 + grp;
    #pragma unroll
    for (int j2 = 0; j2 < 8; j2++) {
        const int cidx = h * 32 + j2 * 4 + tg;    // f16x2 units
        uint32_t h2, l2;
        split2h(o[j2][0] * inv0, o[j2][1] * inv0, h2, l2);
        Chi2[(size_t)row0 * (DD / 2) + cidx] = h2;
        Clo2[(size_t)row0 * (DD / 2) + cidx] = l2;
        split2h(o[j2][2] * inv1, o[j2][3] * inv1, h2, l2);
        Chi2[(size_t)(row0 + 8) * (DD / 2) + cidx] = h2;
        Clo2[(size_t)(row0 + 8) * (DD / 2) + cidx] = l2;
    }
    #undef A_PREFETCH
}

// ---------------------------------------------------------------------------
extern "C" void kernel_launch(void* const* d_in, const int* in_sizes, int n_in,
                              void* d_out, int out_size) {
    const float* x  = (const float*)d_in[0];
    const float* Wq = (const float*)d_in[1];
    const float* bq = (const float*)d_in[2];
    const float* Wk = (const float*)d_in[3];
    const float* bk = (const float*)d_in[4];
    const float* Wv = (const float*)d_in[5];
    const float* bv = (const float*)d_in[6];
    const float* Wo = (const float*)d_in[7];
    const float* bo = (const float*)d_in[8];
    float* out = (float*)d_out;

    __half *xhi, *xlo, *chi, *clo, *qhi, *qlo, *kh, *vh;
    cudaGetSymbolAddress((void**)&xhi, g_xhi);
    cudaGetSymbolAddress((void**)&xlo, g_xlo);
    cudaGetSymbolAddress((void**)&chi, g_chi);
    cudaGetSymbolAddress((void**)&clo, g_clo);
    cudaGetSymbolAddress((void**)&qhi, g_qhi);
    cudaGetSymbolAddress((void**)&qlo, g_qlo);
    cudaGetSymbolAddress((void**)&kh, g_kh);
    cudaGetSymbolAddress((void**)&vh, g_vh);
    __half *wqT, *wkT, *wvT, *woT;
    cudaGetSymbolAddress((void**)&wqT, g_wqT);
    cudaGetSymbolAddress((void**)&wkT, g_wkT);
    cudaGetSymbolAddress((void**)&wvT, g_wvT);
    cudaGetSymbolAddress((void**)&woT, g_woT);

    // 1) input conversions
    int n4 = M_TOT * DD / 4;
    cvt_split4<<<(n4 + 255) / 256, 256>>>((const float4*)x,
                                          (uint32_t*)xhi, (uint32_t*)xlo, n4);
    WJob jq{Wq, wqT}, jk{Wk, wkT}, jv{Wv, wvT}, jo{Wo, woT};
    cvt_wT4<<<dim3(DD / 32, DD / 32, 4), dim3(32, 8)>>>(jq, jk, jv, jo);

    // 2) fused QKV projection (Q split + pre-scaled; K/V plain fp16)
    cudaFuncSetAttribute(gemm_qkv, cudaFuncAttributeMaxDynamicSharedMemorySize, SMEM_GEMM);
    cudaFuncSetAttribute(gemm_hmma, cudaFuncAttributeMaxDynamicSharedMemorySize, SMEM_GEMM);
    QKVJob job;
    job.bT[0] = wqT; job.bias[0] = bq;
    job.chi[0] = (uint32_t*)qhi; job.clo[0] = (uint32_t*)qlo;
    job.scale[0] = 0.125f * 1.44269504f;
    job.bT[1] = wkT; job.bias[1] = bk;
    job.chi[1] = (uint32_t*)kh; job.clo[1] = nullptr;
    job.scale[1] = 1.0f;
    job.bT[2] = wvT; job.bias[2] = bv;
    job.chi[2] = (uint32_t*)vh; job.clo[2] = nullptr;
    job.scale[2] = 1.0f;
    dim3 gq(3 * DD / CTA_N, M_TOT / CTA_M);   // (24, 32) = 768 CTAs
    gemm_qkv<<<gq, 256, SMEM_GEMM>>>(xhi, xlo, job, M_TOT, DD, DD);

    // 3) attention -> ctx fp16 hi/lo
    cudaFuncSetAttribute(attn_hmma, cudaFuncAttributeMaxDynamicSharedMemorySize, SMEM_ATTN);
    attn_hmma<<<dim3(SS / 64, HH, BB), 128, SMEM_ATTN>>>(
        qhi, qlo, kh, vh, (uint32_t*)chi, (uint32_t*)clo);

    // 4) output projection -> fp32 out
    dim3 gg(DD / CTA_N, M_TOT / CTA_M);
    gemm_hmma<<<gg, 256, SMEM_GEMM>>>(chi, clo, woT, bo, out, M_TOT, DD, DD);
}

// round 15
// speedup vs baseline: 1.5837x; 1.0979x over previous
#include <cuda_runtime.h>
#include <cuda_fp16.h>
#include <cstdint>
#include <math.h>

#define BB 2
#define SS 2048
#define DD 1024
#define HH 16
#define HD 64
#define M_TOT (BB*SS)   // 4096

// ---------------------------------------------------------------------------
// Scratch (__device__ globals: allocation-free per harness rules)
// ---------------------------------------------------------------------------
__device__ __half g_xhi[M_TOT * DD];
__device__ __half g_xlo[M_TOT * DD];
__device__ __half g_chi[M_TOT * DD];
__device__ __half g_clo[M_TOT * DD];

__device__ __half g_qhi[M_TOT * DD];
__device__ __half g_qlo[M_TOT * DD];
__device__ __half g_kh[M_TOT * DD];
__device__ __half g_vh[M_TOT * DD];

__device__ __half g_wqT[DD * DD];
__device__ __half g_wkT[DD * DD];
__device__ __half g_wvT[DD * DD];
__device__ __half g_woT[DD * DD];

// ---------------------------------------------------------------------------
// helpers
// ---------------------------------------------------------------------------
__device__ __forceinline__ uint32_t smem_u32(const void* p) {
    uint32_t a;
    asm("{ .reg .u64 t; cvta.to.shared.u64 t, %1; cvt.u32.u64 %0, t; }" : "=r"(a) : "l"(p));
    return a;
}
__device__ __forceinline__ void ldmatrix_x4(uint32_t& r0, uint32_t& r1, uint32_t& r2,
                                            uint32_t& r3, uint32_t addr) {
    asm volatile("ldmatrix.sync.aligned.m8n8.x4.shared.b16 {%0,%1,%2,%3}, [%4];"
                 : "=r"(r0), "=r"(r1), "=r"(r2), "=r"(r3) : "r"(addr));
}
__device__ __forceinline__ void ldmatrix_x4_trans(uint32_t& r0, uint32_t& r1, uint32_t& r2,
                                                  uint32_t& r3, uint32_t addr) {
    asm volatile("ldmatrix.sync.aligned.m8n8.x4.trans.shared.b16 {%0,%1,%2,%3}, [%4];"
                 : "=r"(r0), "=r"(r1), "=r"(r2), "=r"(r3) : "r"(addr));
}
__device__ __forceinline__ void mma_f16(float* d, const uint32_t* a, const uint32_t* b) {
    asm volatile(
        "mma.sync.aligned.m16n8k16.row.col.f32.f16.f16.f32 "
        "{%0,%1,%2,%3}, {%4,%5,%6,%7}, {%8,%9}, {%0,%1,%2,%3};"
        : "+f"(d[0]), "+f"(d[1]), "+f"(d[2]), "+f"(d[3])
        : "r"(a[0]), "r"(a[1]), "r"(a[2]), "r"(a[3]), "r"(b[0]), "r"(b[1]));
}
// fast raw exp2 (args <= 0, bounded; -inf -> 0)
__device__ __forceinline__ float ex2(float x) {
    float r;
    asm("ex2.approx.ftz.f32 %0, %1;" : "=f"(r) : "f"(x));
    return r;
}
// fp16 split: pack (x,y) into f16x2 hi-pair + residual lo-pair
__device__ __forceinline__ void split2h(float x, float y, uint32_t& hi, uint32_t& lo) {
    __half2 h = __floats2half2_rn(x, y);
    float2 f = __half22float2(h);
    __half2 l = __floats2half2_rn(x - f.x, y - f.y);
    hi = *reinterpret_cast<uint32_t*>(&h);
    lo = *reinterpret_cast<uint32_t*>(&l);
}
__device__ __forceinline__ uint32_t pack_h2(float x, float y) {
    __half2 h = __floats2half2_rn(x, y);
    return *reinterpret_cast<uint32_t*>(&h);
}
#define CP16(d, s) asm volatile("cp.async.cg.shared.global [%0], [%1], 16;" :: "r"(d), "l"(s))
#define CP_COMMIT() asm volatile("cp.async.commit_group;" ::: "memory")
#define CP_WAIT0()  asm volatile("cp.async.wait_group 0;" ::: "memory")
// SW128 swizzle (1024B atoms)
#define SWZ(b) ((uint32_t)(b) ^ ((((uint32_t)(b)) >> 3) & 0x70u))

// ---------------------------------------------------------------------------
// fp32 -> fp16 hi/lo split (elementwise, vectorized)
// ---------------------------------------------------------------------------
__global__ void cvt_split4(const float4* __restrict__ in,
                           uint32_t* __restrict__ hi,
                           uint32_t* __restrict__ lo, int n4) {
    int i = blockIdx.x * blockDim.x + threadIdx.x;
    if (i >= n4) return;
    float4 v = in[i];
    uint32_t h0, l0, h1, l1;
    split2h(v.x, v.y, h0, l0);
    split2h(v.z, v.w, h1, l1);
    hi[2*i]   = h0;
    hi[2*i+1] = h1;
    lo[2*i]   = l0;
    lo[2*i+1] = l1;
}

// ---------------------------------------------------------------------------
// W[K][N] fp32 -> transposed plain fp16 [N][K]; 4 weights in one launch
// ---------------------------------------------------------------------------
struct WJob { const float* W; __half* hT; };

__global__ void cvt_wT4(WJob j0, WJob j1, WJob j2, WJob j3) {
    __shared__ float t[32][33];
    WJob j = (blockIdx.z == 0) ? j0 : (blockIdx.z == 1) ? j1 : (blockIdx.z == 2) ? j2 : j3;
    int n0 = blockIdx.x * 32, k0 = blockIdx.y * 32;
    int tx = threadIdx.x, ty = threadIdx.y;
    #pragma unroll
    for (int r = 0; r < 32; r += 8)
        t[ty + r][tx] = j.W[(size_t)(k0 + ty + r) * DD + n0 + tx];
    __syncthreads();
    #pragma unroll
    for (int r = 0; r < 32; r += 8) {
        float v = t[tx][ty + r];
        j.hT[(size_t)(n0 + ty + r) * DD + k0 + tx] = __float2half_rn(v);
    }
}

// ---------------------------------------------------------------------------
// GEMM geometry: A hi/lo + B plain = 3 tiles/stage
// ---------------------------------------------------------------------------
#define CTA_M 128
#define CTA_N 128
#define KC 32
#define LDT 40
#define G_TILE_B (128 * LDT * 2)           // 10240 B
#define G_STAGE_B (3 * G_TILE_B)           // 30720 B
#define SMEM_GEMM (2 * G_STAGE_B)          // 61440 B

// ---------------------------------------------------------------------------
// Fused QKV GEMM: proj = blockIdx.x / 8.
// Q (proj 0): 2-term (xhi+xlo), split hi/lo output.
// K/V (proj 1,2): 1-term (xhi only — lo term is below fp16 storage rounding),
//                 plain fp16 output.
// ---------------------------------------------------------------------------
struct QKVJob {
    const __half* bT[3];
    const float*  bias[3];
    uint32_t*     chi[3];
    uint32_t*     clo[3];   // null -> plain fp16 output, 1-term compute
    float         scale[3];
};

__global__ void __launch_bounds__(256, 2) gemm_qkv(
    const __half* __restrict__ Ahi, const __half* __restrict__ Alo,
    QKVJob job, int M, int N, int K) {
    extern __shared__ __half smG[];
    const uint32_t sbase = smem_u32(smG);

    const int proj = blockIdx.x >> 3;
    const __half* __restrict__ BT = job.bT[proj];
    const float* __restrict__ bias = job.bias[proj];
    uint32_t* __restrict__ Chi2 = job.chi[proj];
    uint32_t* __restrict__ Clo2 = job.clo[proj];
    const float scale = job.scale[proj];
    const bool two_term = (proj == 0);

    const int tid  = threadIdx.x;
    const int wid  = tid >> 5;
    const int lane = tid & 31;
    const int warp_m = wid & 1;
    const int warp_n = wid >> 1;
    const int m0 = blockIdx.y * CTA_M;
    const int n0 = (blockIdx.x & 7) * CTA_N;

    float acc[4][4][4];
    #pragma unroll
    for (int i = 0; i < 4; i++)
        #pragma unroll
        for (int j = 0; j < 4; j++)
            #pragma unroll
            for (int e = 0; e < 4; e++) acc[i][j][e] = 0.f;

    const int lm_r  = lane & 7;
    const int lm_m4 = lane >> 3;
    const int a_row = warp_m * 64 + (lm_m4 & 1) * 8 + lm_r;
    const int a_kof = (lm_m4 >> 1) * 8;
    const int b_row4 = warp_n * 32 + (lane >> 4) * 8 + lm_r;
    const int b_kof4 = ((lane >> 3) & 1) * 8;

    const int ld_row = tid >> 2, ld_s = tid & 3;
    const int nchunks = K / KC;

    #define G_PREFETCH(stage, k0_)  do {                                              \
        uint32_t dstb = sbase + (uint32_t)(stage) * G_STAGE_B;                        \
        _Pragma("unroll")                                                             \
        for (int t = 0; t < 2; t++) {                                                 \
            int row = ld_row + t * 64;                                                \
            uint32_t so = (uint32_t)(row * LDT + ld_s * 8) * 2;                       \
            CP16(dstb + so,               Ahi + (size_t)(m0 + row) * K + (k0_) + ld_s * 8); \
            if (two_term)                                                             \
                CP16(dstb + G_TILE_B + so, Alo + (size_t)(m0 + row) * K + (k0_) + ld_s * 8); \
            CP16(dstb + 2*G_TILE_B + so,  BT  + (size_t)(n0 + row) * K + (k0_) + ld_s * 8); \
        }                                                                             \
        CP_COMMIT();                                                                  \
    } while (0)

    G_PREFETCH(0, 0);

    for (int c = 0; c < nchunks; c++) {
        CP_WAIT0();
        __syncthreads();
        if (c + 1 < nchunks) G_PREFETCH((c + 1) & 1, (c + 1) * KC);

        const uint32_t sb = sbase + (uint32_t)(c & 1) * G_STAGE_B;
        const uint32_t sAhi = sb, sAlo = sb + G_TILE_B, sB = sb + 2 * G_TILE_B;

        #pragma unroll
        for (int ks = 0; ks < 2; ks++) {
            uint32_t ahi[4][4], alo[4][4], bh[4][2];
            #pragma unroll
            for (int i = 0; i < 4; i++) {
                uint32_t off = (uint32_t)((a_row + i * 16) * LDT + ks * 16 + a_kof) * 2;
                ldmatrix_x4(ahi[i][0], ahi[i][1], ahi[i][2], ahi[i][3], sAhi + off);
                if (two_term)
                    ldmatrix_x4(alo[i][0], alo[i][1], alo[i][2], alo[i][3], sAlo + off);
            }
            #pragma unroll
            for (int j2 = 0; j2 < 4; j2 += 2) {
                uint32_t off = (uint32_t)((b_row4 + j2 * 8) * LDT + ks * 16 + b_kof4) * 2;
                ldmatrix_x4(bh[j2][0], bh[j2][1], bh[j2+1][0], bh[j2+1][1], sB + off);
            }
            #pragma unroll
            for (int i = 0; i < 4; i++)
                #pragma unroll
                for (int j = 0; j < 4; j++)
                    mma_f16(acc[i][j], ahi[i], bh[j]);
            if (two_term) {
                #pragma unroll
                for (int i = 0; i < 4; i++)
                    #pragma unroll
                    for (int j = 0; j < 4; j++)
                        mma_f16(acc[i][j], alo[i], bh[j]);
            }
        }
    }

    __syncthreads();
    const int grp = lane >> 2, tg = lane & 3;
    #pragma unroll
    for (int i = 0; i < 4; i++) {
        int row0 = m0 + warp_m * 64 + i * 16 + grp;
        #pragma unroll
        for (int j = 0; j < 4; j++) {
            int col = n0 + warp_n * 32 + j * 8 + tg * 2;
            float b0 = bias[col], b1 = bias[col + 1];
            float v0 = (acc[i][j][0] + b0) * scale, v1 = (acc[i][j][1] + b1) * scale;
            float v2 = (acc[i][j][2] + b0) * scale, v3 = (acc[i][j][3] + b1) * scale;
            if (Clo2) {
                uint32_t h2, l2;
                split2h(v0, v1, h2, l2);
                Chi2[(size_t)row0 * (N / 2) + col / 2] = h2;
                Clo2[(size_t)row0 * (N / 2) + col / 2] = l2;
                split2h(v2, v3, h2, l2);
                Chi2[(size_t)(row0 + 8) * (N / 2) + col / 2] = h2;
                Clo2[(size_t)(row0 + 8) * (N / 2) + col / 2] = l2;
            } else {
                Chi2[(size_t)row0 * (N / 2) + col / 2] = pack_h2(v0, v1);
                Chi2[(size_t)(row0 + 8) * (N / 2) + col / 2] = pack_h2(v2, v3);
            }
        }
    }
    #undef G_PREFETCH
}

// ---------------------------------------------------------------------------
// Out-projection GEMM: ctx hi/lo @ WoT plain -> fp32 out (2-term)
// ---------------------------------------------------------------------------
__global__ void __launch_bounds__(256, 2) gemm_hmma(
    const __half* __restrict__ Ahi, const __half* __restrict__ Alo,
    const __half* __restrict__ BT, const float* __restrict__ bias,
    float* __restrict__ Cf, int M, int N, int K) {
    extern __shared__ __half smG[];
    const uint32_t sbase = smem_u32(smG);

    const int tid  = threadIdx.x;
    const int wid  = tid >> 5;
    const int lane = tid & 31;
    const int warp_m = wid & 1;
    const int warp_n = wid >> 1;
    const int m0 = blockIdx.y * CTA_M;
    const int n0 = blockIdx.x * CTA_N;

    float acc[4][4][4];
    #pragma unroll
    for (int i = 0; i < 4; i++)
        #pragma unroll
        for (int j = 0; j < 4; j++)
            #pragma unroll
            for (int e = 0; e < 4; e++) acc[i][j][e] = 0.f;

    const int lm_r  = lane & 7;
    const int lm_m4 = lane >> 3;
    const int a_row = warp_m * 64 + (lm_m4 & 1) * 8 + lm_r;
    const int a_kof = (lm_m4 >> 1) * 8;
    const int b_row4 = warp_n * 32 + (lane >> 4) * 8 + lm_r;
    const int b_kof4 = ((lane >> 3) & 1) * 8;

    const int ld_row = tid >> 2, ld_s = tid & 3;
    const int nchunks = K / KC;

    #define G_PREFETCH(stage, k0_)  do {                                              \
        uint32_t dstb = sbase + (uint32_t)(stage) * G_STAGE_B;                        \
        _Pragma("unroll")                                                             \
        for (int t = 0; t < 2; t++) {                                                 \
            int row = ld_row + t * 64;                                                \
            uint32_t so = (uint32_t)(row * LDT + ld_s * 8) * 2;                       \
            CP16(dstb + so,               Ahi + (size_t)(m0 + row) * K + (k0_) + ld_s * 8); \
            CP16(dstb + G_TILE_B + so,    Alo + (size_t)(m0 + row) * K + (k0_) + ld_s * 8); \
            CP16(dstb + 2*G_TILE_B + so,  BT  + (size_t)(n0 + row) * K + (k0_) + ld_s * 8); \
        }                                                                             \
        CP_COMMIT();                                                                  \
    } while (0)

    G_PREFETCH(0, 0);

    for (int c = 0; c < nchunks; c++) {
        CP_WAIT0();
        __syncthreads();
        if (c + 1 < nchunks) G_PREFETCH((c + 1) & 1, (c + 1) * KC);

        const uint32_t sb = sbase + (uint32_t)(c & 1) * G_STAGE_B;
        const uint32_t sAhi = sb, sAlo = sb + G_TILE_B, sB = sb + 2 * G_TILE_B;

        #pragma unroll
        for (int ks = 0; ks < 2; ks++) {
            uint32_t ahi[4][4], alo[4][4], bh[4][2];
            #pragma unroll
            for (int i = 0; i < 4; i++) {
                uint32_t off = (uint32_t)((a_row + i * 16) * LDT + ks * 16 + a_kof) * 2;
                ldmatrix_x4(ahi[i][0], ahi[i][1], ahi[i][2], ahi[i][3], sAhi + off);
                ldmatrix_x4(alo[i][0], alo[i][1], alo[i][2], alo[i][3], sAlo + off);
            }
            #pragma unroll
            for (int j2 = 0; j2 < 4; j2 += 2) {
                uint32_t off = (uint32_t)((b_row4 + j2 * 8) * LDT + ks * 16 + b_kof4) * 2;
                ldmatrix_x4(bh[j2][0], bh[j2][1], bh[j2+1][0], bh[j2+1][1], sB + off);
            }
            #pragma unroll
            for (int i = 0; i < 4; i++)
                #pragma unroll
                for (int j = 0; j < 4; j++) {
                    mma_f16(acc[i][j], ahi[i], bh[j]);
                    mma_f16(acc[i][j], alo[i], bh[j]);
                }
        }
    }

    __syncthreads();
    const int grp = lane >> 2, tg = lane & 3;
    #pragma unroll
    for (int i = 0; i < 4; i++) {
        int row0 = m0 + warp_m * 64 + i * 16 + grp;
        #pragma unroll
        for (int j = 0; j < 4; j++) {
            int col = n0 + warp_n * 32 + j * 8 + tg * 2;
            float b0 = bias[col], b1 = bias[col + 1];
            float* p0 = Cf + (size_t)row0 * N + col;
            p0[0] = acc[i][j][0] + b0;
            p0[1] = acc[i][j][1] + b1;
            float* p1 = Cf + (size_t)(row0 + 8) * N + col;
            p1[0] = acc[i][j][2] + b0;
            p1[1] = acc[i][j][3] + b1;
        }
    }
    #undef G_PREFETCH
}

// ---------------------------------------------------------------------------
// fp16 HMMA causal flash attention (round-14 body, unchanged)
// ---------------------------------------------------------------------------
#define A_TILE_B 8192                      // 64 rows * 128 B
#define A_STAGE_B (2 * A_TILE_B)           // 16384 B (K + V)
#define SMEM_ATTN (2 * A_STAGE_B)          // 32768 B

__global__ void __launch_bounds__(128, 3) attn_hmma(
    const __half* __restrict__ Qhi, const __half* __restrict__ Qlo,
    const __half* __restrict__ Kh, const __half* __restrict__ Vh,
    uint32_t* __restrict__ Chi2, uint32_t* __restrict__ Clo2) {
    extern __shared__ __half smA[];
    const uint32_t sbase = smem_u32(smA);

    const int tid  = threadIdx.x;
    const int wid  = tid >> 5;
    const int lane = tid & 31;
    const int grp  = lane >> 2, tg = lane & 3;
    const int qt = (int)gridDim.x - 1 - (int)blockIdx.x;   // heavy tiles first
    const int h  = blockIdx.y;
    const int b  = blockIdx.z;
    const int q0 = qt * 64;

    const int a_row = wid * 16 + ((lane >> 3) & 1) * 8 + (lane & 7);
    const int a_kby = (((lane >> 4) & 1) * 8) * 2;
    const int k_row4 = (lane >> 4) * 8 + (lane & 7);
    const int k_kby4 = (((lane >> 3) & 1) * 8) * 2;
    const int v_row4 = ((lane >> 3) & 1) * 8 + (lane & 7);
    const int v_cby4 = ((lane >> 4) * 8) * 2;

    // --- stage Q hi/lo through stage area (swizzled), preload frags ---
    #pragma unroll
    for (int t = 0; t < 4; t++) {
        int idx = tid + t * 128;
        int r = idx >> 3, s = idx & 7;
        size_t g = (size_t)(b * SS + q0 + r) * DD + h * HD + s * 8;
        uint32_t so = SWZ(r * 128 + s * 16);
        *(uint4*)((char*)smA + so) = *(const uint4*)(Qhi + g);
        *(uint4*)((char*)smA + A_TILE_B + so) = *(const uint4*)(Qlo + g);
    }
    __syncthreads();
    uint32_t qh[4][4], ql[4][4];
    #pragma unroll
    for (int ks = 0; ks < 4; ks++) {
        uint32_t off = SWZ(a_row * 128 + ks * 32 + a_kby);
        ldmatrix_x4(qh[ks][0], qh[ks][1], qh[ks][2], qh[ks][3], sbase + off);
        ldmatrix_x4(ql[ks][0], ql[ks][1], ql[ks][2], ql[ks][3], sbase + A_TILE_B + off);
    }
    __syncthreads();

    #define A_PREFETCH(stage, k0_)  do {                                              \
        uint32_t dstb = sbase + (uint32_t)(stage) * A_STAGE_B;                        \
        _Pragma("unroll")                                                             \
        for (int t = 0; t < 4; t++) {                                                 \
            int idx = tid + t * 128;                                                  \
            int r = idx >> 3, s = idx & 7;                                            \
            size_t g = (size_t)(b * SS + (k0_) + r) * DD + h * HD + s * 8;            \
            uint32_t so = SWZ(r * 128 + s * 16);                                      \
            CP16(dstb + so,              Kh + g);                                     \
            CP16(dstb + A_TILE_B + so,   Vh + g);                                     \
        }                                                                             \
        CP_COMMIT();                                                                  \
    } while (0)

    A_PREFETCH(0, 0);

    float m0 = -INFINITY, m1 = -INFINITY, l0 = 0.f, l1 = 0.f;
    float o[8][4];
    #pragma unroll
    for (int j = 0; j < 8; j++)
        #pragma unroll
        for (int e = 0; e < 4; e++) o[j][e] = 0.f;

    for (int kt = 0; kt <= qt; kt++) {
        CP_WAIT0();
        __syncthreads();
        if (kt < qt) A_PREFETCH((kt + 1) & 1, (kt + 1) * 64);

        const uint32_t sb = sbase + (uint32_t)(kt & 1) * A_STAGE_B;
        const uint32_t sKh_u = sb, sVh_u = sb + A_TILE_B;

        // --- S = Q K^T (2-term: Qh*K + Ql*K) ---
        float sc[8][4];
        #pragma unroll
        for (int j = 0; j < 8; j++)
            #pragma unroll
            for (int e = 0; e < 4; e++) sc[j][e] = 0.f;

        #pragma unroll
        for (int ks = 0; ks < 4; ks++) {
            uint32_t kb[8][2];
            #pragma unroll
            for (int j2 = 0; j2 < 8; j2 += 2) {
                uint32_t off = SWZ((j2 * 8 + k_row4) * 128 + ks * 32 + k_kby4);
                ldmatrix_x4(kb[j2][0], kb[j2][1], kb[j2+1][0], kb[j2+1][1], sKh_u + off);
            }
            #pragma unroll
            for (int j = 0; j < 8; j++) mma_f16(sc[j], qh[ks], kb[j]);
            #pragma unroll
            for (int j = 0; j < 8; j++) mma_f16(sc[j], ql[ks], kb[j]);
        }

        // --- causal mask on diagonal tile ---
        if (kt == qt) {
            const int qr0 = wid * 16 + grp;
            #pragma unroll
            for (int j = 0; j < 8; j++) {
                int kc = j * 8 + 2 * tg;
                if (kc     > qr0)     sc[j][0] = -INFINITY;
                if (kc + 1 > qr0)     sc[j][1] = -INFINITY;
                if (kc     > qr0 + 8) sc[j][2] = -INFINITY;
                if (kc + 1 > qr0 + 8) sc[j][3] = -INFINITY;
            }
        }

        // --- online softmax in exp2 domain, raw ex2.approx ---
        float mx0 = -INFINITY, mx1 = -INFINITY;
        #pragma unroll
        for (int j = 0; j < 8; j++) {
            mx0 = fmaxf(mx0, fmaxf(sc[j][0], sc[j][1]));
            mx1 = fmaxf(mx1, fmaxf(sc[j][2], sc[j][3]));
        }
        mx0 = fmaxf(mx0, __shfl_xor_sync(0xffffffffu, mx0, 1));
        mx0 = fmaxf(mx0, __shfl_xor_sync(0xffffffffu, mx0, 2));
        mx1 = fmaxf(mx1, __shfl_xor_sync(0xffffffffu, mx1, 1));
        mx1 = fmaxf(mx1, __shfl_xor_sync(0xffffffffu, mx1, 2));
        float mn0 = fmaxf(m0, mx0), mn1 = fmaxf(m1, mx1);
        float al0 = ex2(m0 - mn0), al1 = ex2(m1 - mn1);
        float s0 = 0.f, s1 = 0.f;
        #pragma unroll
        for (int j = 0; j < 8; j++) {
            sc[j][0] = ex2(sc[j][0] - mn0);
            sc[j][1] = ex2(sc[j][1] - mn0);
            sc[j][2] = ex2(sc[j][2] - mn1);
            sc[j][3] = ex2(sc[j][3] - mn1);
            s0 += sc[j][0] + sc[j][1];
            s1 += sc[j][2] + sc[j][3];
        }
        s0 += __shfl_xor_sync(0xffffffffu, s0, 1);
        s0 += __shfl_xor_sync(0xffffffffu, s0, 2);
        s1 += __shfl_xor_sync(0xffffffffu, s1, 1);
        s1 += __shfl_xor_sync(0xffffffffu, s1, 2);
        l0 = l0 * al0 + s0;  m0 = mn0;
        l1 = l1 * al1 + s1;  m1 = mn1;
        #pragma unroll
        for (int j = 0; j < 8; j++) {
            o[j][0] *= al0; o[j][1] *= al0;
            o[j][2] *= al1; o[j][3] *= al1;
        }

        // --- O += P V (2-term: Ph*V + Pl*V) ---
        #pragma unroll
        for (int ks = 0; ks < 4; ks++) {
            uint32_t ph[4], pl[4];
            split2h(sc[2*ks][0],   sc[2*ks][1],   ph[0], pl[0]);
            split2h(sc[2*ks][2],   sc[2*ks][3],   ph[1], pl[1]);
            split2h(sc[2*ks+1][0], sc[2*ks+1][1], ph[2], pl[2]);
            split2h(sc[2*ks+1][2], sc[2*ks+1][3], ph[3], pl[3]);
            uint32_t vb[8][2];
            #pragma unroll
            for (int j2 = 0; j2 < 8; j2 += 2) {
                uint32_t off = SWZ((ks * 16 + v_row4) * 128 + j2 * 16 + v_cby4);
                ldmatrix_x4_trans(vb[j2][0], vb[j2][1], vb[j2+1][0], vb[j2+1][1], sVh_u + off);
            }
            #pragma unroll
            for (int j2 = 0; j2 < 8; j2++) mma_f16(o[j2], ph, vb[j2]);
            #pragma unroll
            for (int j2 = 0; j2 < 8; j2++) mma_f16(o[j2], pl, vb[j2]);
        }
    }

    // --- epilogue: ctx = O / l, written as fp16 hi/lo pairs ---
    const float inv0 = 1.f / l0, inv1 = 1.f / l1;
    const int row0 = b * SS + q0 + wid * 16 + grp;
    #pragma unroll
    for (int j2 = 0; j2 < 8; j2++) {
        const int cidx = h * 32 + j2 * 4 + tg;    // f16x2 units
        uint32_t h2, l2;
        split2h(o[j2][0] * inv0, o[j2][1] * inv0, h2, l2);
        Chi2[(size_t)row0 * (DD / 2) + cidx] = h2;
        Clo2[(size_t)row0 * (DD / 2) + cidx] = l2;
        split2h(o[j2][2] * inv1, o[j2][3] * inv1, h2, l2);
        Chi2[(size_t)(row0 + 8) * (DD / 2) + cidx] = h2;
        Clo2[(size_t)(row0 + 8) * (DD / 2) + cidx] = l2;
    }
    #undef A_PREFETCH
}

// ---------------------------------------------------------------------------
extern "C" void kernel_launch(void* const* d_in, const int* in_sizes, int n_in,
                              void* d_out, int out_size) {
    const float* x  = (const float*)d_in[0];
    const float* Wq = (const float*)d_in[1];
    const float* bq = (const float*)d_in[2];
    const float* Wk = (const float*)d_in[3];
    const float* bk = (const float*)d_in[4];
    const float* Wv = (const float*)d_in[5];
    const float* bv = (const float*)d_in[6];
    const float* Wo = (const float*)d_in[7];
    const float* bo = (const float*)d_in[8];
    float* out = (float*)d_out;

    __half *xhi, *xlo, *chi, *clo, *qhi, *qlo, *kh, *vh;
    cudaGetSymbolAddress((void**)&xhi, g_xhi);
    cudaGetSymbolAddress((void**)&xlo, g_xlo);
    cudaGetSymbolAddress((void**)&chi, g_chi);
    cudaGetSymbolAddress((void**)&clo, g_clo);
    cudaGetSymbolAddress((void**)&qhi, g_qhi);
    cudaGetSymbolAddress((void**)&qlo, g_qlo);
    cudaGetSymbolAddress((void**)&kh, g_kh);
    cudaGetSymbolAddress((void**)&vh, g_vh);
    __half *wqT, *wkT, *wvT, *woT;
    cudaGetSymbolAddress((void**)&wqT, g_wqT);
    cudaGetSymbolAddress((void**)&wkT, g_wkT);
    cudaGetSymbolAddress((void**)&wvT, g_wvT);
    cudaGetSymbolAddress((void**)&woT, g_woT);

    // 1) input conversions
    int n4 = M_TOT * DD / 4;
    cvt_split4<<<(n4 + 255) / 256, 256>>>((const float4*)x,
                                          (uint32_t*)xhi, (uint32_t*)xlo, n4);
    WJob jq{Wq, wqT}, jk{Wk, wkT}, jv{Wv, wvT}, jo{Wo, woT};
    cvt_wT4<<<dim3(DD / 32, DD / 32, 4), dim3(32, 8)>>>(jq, jk, jv, jo);

    // 2) fused QKV projection (Q 2-term split output; K/V 1-term plain)
    cudaFuncSetAttribute(gemm_qkv, cudaFuncAttributeMaxDynamicSharedMemorySize, SMEM_GEMM);
    cudaFuncSetAttribute(gemm_hmma, cudaFuncAttributeMaxDynamicSharedMemorySize, SMEM_GEMM);
    QKVJob job;
    job.bT[0] = wqT; job.bias[0] = bq;
    job.chi[0] = (uint32_t*)qhi; job.clo[0] = (uint32_t*)qlo;
    job.scale[0] = 0.125f * 1.44269504f;
    job.bT[1] = wkT; job.bias[1] = bk;
    job.chi[1] = (uint32_t*)kh; job.clo[1] = nullptr;
    job.scale[1] = 1.0f;
    job.bT[2] = wvT; job.bias[2] = bv;
    job.chi[2] = (uint32_t*)vh; job.clo[2] = nullptr;
    job.scale[2] = 1.0f;
    dim3 gq(3 * DD / CTA_N, M_TOT / CTA_M);   // (24, 32) = 768 CTAs
    gemm_qkv<<<gq, 256, SMEM_GEMM>>>(xhi, xlo, job, M_TOT, DD, DD);

    // 3) attention -> ctx fp16 hi/lo
    cudaFuncSetAttribute(attn_hmma, cudaFuncAttributeMaxDynamicSharedMemorySize, SMEM_ATTN);
    attn_hmma<<<dim3(SS / 64, HH, BB), 128, SMEM_ATTN>>>(
        qhi, qlo, kh, vh, (uint32_t*)chi, (uint32_t*)clo);

    // 4) output projection -> fp32 out
    dim3 gg(DD / CTA_N, M_TOT / CTA_M);
    gemm_hmma<<<gg, 256, SMEM_GEMM>>>(chi, clo, woT, bo, out, M_TOT, DD, DD);
}

// round 16
// speedup vs baseline: 1.8978x; 1.1983x over previous
#include <cuda_runtime.h>
#include <cuda_fp16.h>
#include <cstdint>
#include <math.h>

#define BB 2
#define SS 2048
#define DD 1024
#define HH 16
#define HD 64
#define M_TOT (BB*SS)   // 4096

// ---------------------------------------------------------------------------
// Scratch (__device__ globals: allocation-free per harness rules)
// ---------------------------------------------------------------------------
__device__ __half g_xhi[M_TOT * DD];
__device__ __half g_xlo[M_TOT * DD];
__device__ __half g_ctx[M_TOT * DD];      // plain fp16 ctx

__device__ __half g_qhi[M_TOT * DD];
__device__ __half g_qlo[M_TOT * DD];
__device__ __half g_kh[M_TOT * DD];
__device__ __half g_vh[M_TOT * DD];

__device__ __half g_wqT[DD * DD];
__device__ __half g_wkT[DD * DD];
__device__ __half g_wvT[DD * DD];
__device__ __half g_woT[DD * DD];

// ---------------------------------------------------------------------------
// helpers
// ---------------------------------------------------------------------------
__device__ __forceinline__ uint32_t smem_u32(const void* p) {
    uint32_t a;
    asm("{ .reg .u64 t; cvta.to.shared.u64 t, %1; cvt.u32.u64 %0, t; }" : "=r"(a) : "l"(p));
    return a;
}
__device__ __forceinline__ void ldmatrix_x4(uint32_t& r0, uint32_t& r1, uint32_t& r2,
                                            uint32_t& r3, uint32_t addr) {
    asm volatile("ldmatrix.sync.aligned.m8n8.x4.shared.b16 {%0,%1,%2,%3}, [%4];"
                 : "=r"(r0), "=r"(r1), "=r"(r2), "=r"(r3) : "r"(addr));
}
__device__ __forceinline__ void ldmatrix_x4_trans(uint32_t& r0, uint32_t& r1, uint32_t& r2,
                                                  uint32_t& r3, uint32_t addr) {
    asm volatile("ldmatrix.sync.aligned.m8n8.x4.trans.shared.b16 {%0,%1,%2,%3}, [%4];"
                 : "=r"(r0), "=r"(r1), "=r"(r2), "=r"(r3) : "r"(addr));
}
__device__ __forceinline__ void mma_f16(float* d, const uint32_t* a, const uint32_t* b) {
    asm volatile(
        "mma.sync.aligned.m16n8k16.row.col.f32.f16.f16.f32 "
        "{%0,%1,%2,%3}, {%4,%5,%6,%7}, {%8,%9}, {%0,%1,%2,%3};"
        : "+f"(d[0]), "+f"(d[1]), "+f"(d[2]), "+f"(d[3])
        : "r"(a[0]), "r"(a[1]), "r"(a[2]), "r"(a[3]), "r"(b[0]), "r"(b[1]));
}
// fast raw exp2 (args <= 0, bounded; -inf -> 0)
__device__ __forceinline__ float ex2(float x) {
    float r;
    asm("ex2.approx.ftz.f32 %0, %1;" : "=f"(r) : "f"(x));
    return r;
}
// fp16 split: pack (x,y) into f16x2 hi-pair + residual lo-pair
__device__ __forceinline__ void split2h(float x, float y, uint32_t& hi, uint32_t& lo) {
    __half2 h = __floats2half2_rn(x, y);
    float2 f = __half22float2(h);
    __half2 l = __floats2half2_rn(x - f.x, y - f.y);
    hi = *reinterpret_cast<uint32_t*>(&h);
    lo = *reinterpret_cast<uint32_t*>(&l);
}
__device__ __forceinline__ uint32_t pack_h2(float x, float y) {
    __half2 h = __floats2half2_rn(x, y);
    return *reinterpret_cast<uint32_t*>(&h);
}
#define CP16(d, s) asm volatile("cp.async.cg.shared.global [%0], [%1], 16;" :: "r"(d), "l"(s))
#define CP_COMMIT() asm volatile("cp.async.commit_group;" ::: "memory")
#define CP_WAIT0()  asm volatile("cp.async.wait_group 0;" ::: "memory")
// SW128 swizzle (1024B atoms)
#define SWZ(b) ((uint32_t)(b) ^ ((((uint32_t)(b)) >> 3) & 0x70u))

// ---------------------------------------------------------------------------
// fp32 -> fp16 hi/lo split (elementwise, vectorized)
// ---------------------------------------------------------------------------
__global__ void cvt_split4(const float4* __restrict__ in,
                           uint32_t* __restrict__ hi,
                           uint32_t* __restrict__ lo, int n4) {
    int i = blockIdx.x * blockDim.x + threadIdx.x;
    if (i >= n4) return;
    float4 v = in[i];
    uint32_t h0, l0, h1, l1;
    split2h(v.x, v.y, h0, l0);
    split2h(v.z, v.w, h1, l1);
    hi[2*i]   = h0;
    hi[2*i+1] = h1;
    lo[2*i]   = l0;
    lo[2*i+1] = l1;
}

// ---------------------------------------------------------------------------
// W[K][N] fp32 -> transposed plain fp16 [N][K]; 4 weights in one launch
// ---------------------------------------------------------------------------
struct WJob { const float* W; __half* hT; };

__global__ void cvt_wT4(WJob j0, WJob j1, WJob j2, WJob j3) {
    __shared__ float t[32][33];
    WJob j = (blockIdx.z == 0) ? j0 : (blockIdx.z == 1) ? j1 : (blockIdx.z == 2) ? j2 : j3;
    int n0 = blockIdx.x * 32, k0 = blockIdx.y * 32;
    int tx = threadIdx.x, ty = threadIdx.y;
    #pragma unroll
    for (int r = 0; r < 32; r += 8)
        t[ty + r][tx] = j.W[(size_t)(k0 + ty + r) * DD + n0 + tx];
    __syncthreads();
    #pragma unroll
    for (int r = 0; r < 32; r += 8) {
        float v = t[tx][ty + r];
        j.hT[(size_t)(n0 + ty + r) * DD + k0 + tx] = __float2half_rn(v);
    }
}

// ---------------------------------------------------------------------------
// GEMM geometry
// ---------------------------------------------------------------------------
#define CTA_M 128
#define CTA_N 128
#define KC 32
#define LDT 40
#define G_TILE_B (128 * LDT * 2)           // 10240 B
#define G_STAGE_B (3 * G_TILE_B)           // 30720 B (QKV: Ahi, Alo, B)
#define SMEM_GEMM (2 * G_STAGE_B)          // 61440 B
#define O_STAGE_B (2 * G_TILE_B)           // 20480 B (out-proj: A, B)
#define SMEM_OPROJ (2 * O_STAGE_B)         // 40960 B

// ---------------------------------------------------------------------------
// Fused QKV GEMM: proj = blockIdx.x / 8.
// Q (proj 0): 2-term (xhi+xlo), split hi/lo output.
// K/V (proj 1,2): 1-term, plain fp16 output.
// ---------------------------------------------------------------------------
struct QKVJob {
    const __half* bT[3];
    const float*  bias[3];
    uint32_t*     chi[3];
    uint32_t*     clo[3];   // null -> plain fp16 output, 1-term compute
    float         scale[3];
};

__global__ void __launch_bounds__(256, 2) gemm_qkv(
    const __half* __restrict__ Ahi, const __half* __restrict__ Alo,
    QKVJob job, int M, int N, int K) {
    extern __shared__ __half smG[];
    const uint32_t sbase = smem_u32(smG);

    const int proj = blockIdx.x >> 3;
    const __half* __restrict__ BT = job.bT[proj];
    const float* __restrict__ bias = job.bias[proj];
    uint32_t* __restrict__ Chi2 = job.chi[proj];
    uint32_t* __restrict__ Clo2 = job.clo[proj];
    const float scale = job.scale[proj];
    const bool two_term = (proj == 0);

    const int tid  = threadIdx.x;
    const int wid  = tid >> 5;
    const int lane = tid & 31;
    const int warp_m = wid & 1;
    const int warp_n = wid >> 1;
    const int m0 = blockIdx.y * CTA_M;
    const int n0 = (blockIdx.x & 7) * CTA_N;

    float acc[4][4][4];
    #pragma unroll
    for (int i = 0; i < 4; i++)
        #pragma unroll
        for (int j = 0; j < 4; j++)
            #pragma unroll
            for (int e = 0; e < 4; e++) acc[i][j][e] = 0.f;

    const int lm_r  = lane & 7;
    const int lm_m4 = lane >> 3;
    const int a_row = warp_m * 64 + (lm_m4 & 1) * 8 + lm_r;
    const int a_kof = (lm_m4 >> 1) * 8;
    const int b_row4 = warp_n * 32 + (lane >> 4) * 8 + lm_r;
    const int b_kof4 = ((lane >> 3) & 1) * 8;

    const int ld_row = tid >> 2, ld_s = tid & 3;
    const int nchunks = K / KC;

    #define G_PREFETCH(stage, k0_)  do {                                              \
        uint32_t dstb = sbase + (uint32_t)(stage) * G_STAGE_B;                        \
        _Pragma("unroll")                                                             \
        for (int t = 0; t < 2; t++) {                                                 \
            int row = ld_row + t * 64;                                                \
            uint32_t so = (uint32_t)(row * LDT + ld_s * 8) * 2;                       \
            CP16(dstb + so,               Ahi + (size_t)(m0 + row) * K + (k0_) + ld_s * 8); \
            if (two_term)                                                             \
                CP16(dstb + G_TILE_B + so, Alo + (size_t)(m0 + row) * K + (k0_) + ld_s * 8); \
            CP16(dstb + 2*G_TILE_B + so,  BT  + (size_t)(n0 + row) * K + (k0_) + ld_s * 8); \
        }                                                                             \
        CP_COMMIT();                                                                  \
    } while (0)

    G_PREFETCH(0, 0);

    for (int c = 0; c < nchunks; c++) {
        CP_WAIT0();
        __syncthreads();
        if (c + 1 < nchunks) G_PREFETCH((c + 1) & 1, (c + 1) * KC);

        const uint32_t sb = sbase + (uint32_t)(c & 1) * G_STAGE_B;
        const uint32_t sAhi = sb, sAlo = sb + G_TILE_B, sB = sb + 2 * G_TILE_B;

        #pragma unroll
        for (int ks = 0; ks < 2; ks++) {
            uint32_t ahi[4][4], alo[4][4], bh[4][2];
            #pragma unroll
            for (int i = 0; i < 4; i++) {
                uint32_t off = (uint32_t)((a_row + i * 16) * LDT + ks * 16 + a_kof) * 2;
                ldmatrix_x4(ahi[i][0], ahi[i][1], ahi[i][2], ahi[i][3], sAhi + off);
                if (two_term)
                    ldmatrix_x4(alo[i][0], alo[i][1], alo[i][2], alo[i][3], sAlo + off);
            }
            #pragma unroll
            for (int j2 = 0; j2 < 4; j2 += 2) {
                uint32_t off = (uint32_t)((b_row4 + j2 * 8) * LDT + ks * 16 + b_kof4) * 2;
                ldmatrix_x4(bh[j2][0], bh[j2][1], bh[j2+1][0], bh[j2+1][1], sB + off);
            }
            #pragma unroll
            for (int i = 0; i < 4; i++)
                #pragma unroll
                for (int j = 0; j < 4; j++)
                    mma_f16(acc[i][j], ahi[i], bh[j]);
            if (two_term) {
                #pragma unroll
                for (int i = 0; i < 4; i++)
                    #pragma unroll
                    for (int j = 0; j < 4; j++)
                        mma_f16(acc[i][j], alo[i], bh[j]);
            }
        }
    }

    __syncthreads();
    const int grp = lane >> 2, tg = lane & 3;
    #pragma unroll
    for (int i = 0; i < 4; i++) {
        int row0 = m0 + warp_m * 64 + i * 16 + grp;
        #pragma unroll
        for (int j = 0; j < 4; j++) {
            int col = n0 + warp_n * 32 + j * 8 + tg * 2;
            float b0 = bias[col], b1 = bias[col + 1];
            float v0 = (acc[i][j][0] + b0) * scale, v1 = (acc[i][j][1] + b1) * scale;
            float v2 = (acc[i][j][2] + b0) * scale, v3 = (acc[i][j][3] + b1) * scale;
            if (Clo2) {
                uint32_t h2, l2;
                split2h(v0, v1, h2, l2);
                Chi2[(size_t)row0 * (N / 2) + col / 2] = h2;
                Clo2[(size_t)row0 * (N / 2) + col / 2] = l2;
                split2h(v2, v3, h2, l2);
                Chi2[(size_t)(row0 + 8) * (N / 2) + col / 2] = h2;
                Clo2[(size_t)(row0 + 8) * (N / 2) + col / 2] = l2;
            } else {
                Chi2[(size_t)row0 * (N / 2) + col / 2] = pack_h2(v0, v1);
                Chi2[(size_t)(row0 + 8) * (N / 2) + col / 2] = pack_h2(v2, v3);
            }
        }
    }
    #undef G_PREFETCH
}

// ---------------------------------------------------------------------------
// Out-projection GEMM: ctx plain fp16 @ WoT plain -> fp32 out (1-term)
// ---------------------------------------------------------------------------
__global__ void __launch_bounds__(256, 2) gemm_hmma(
    const __half* __restrict__ A, const __half* __restrict__ BT,
    const float* __restrict__ bias, float* __restrict__ Cf,
    int M, int N, int K) {
    extern __shared__ __half smG[];
    const uint32_t sbase = smem_u32(smG);

    const int tid  = threadIdx.x;
    const int wid  = tid >> 5;
    const int lane = tid & 31;
    const int warp_m = wid & 1;
    const int warp_n = wid >> 1;
    const int m0 = blockIdx.y * CTA_M;
    const int n0 = blockIdx.x * CTA_N;

    float acc[4][4][4];
    #pragma unroll
    for (int i = 0; i < 4; i++)
        #pragma unroll
        for (int j = 0; j < 4; j++)
            #pragma unroll
            for (int e = 0; e < 4; e++) acc[i][j][e] = 0.f;

    const int lm_r  = lane & 7;
    const int lm_m4 = lane >> 3;
    const int a_row = warp_m * 64 + (lm_m4 & 1) * 8 + lm_r;
    const int a_kof = (lm_m4 >> 1) * 8;
    const int b_row4 = warp_n * 32 + (lane >> 4) * 8 + lm_r;
    const int b_kof4 = ((lane >> 3) & 1) * 8;

    const int ld_row = tid >> 2, ld_s = tid & 3;
    const int nchunks = K / KC;

    #define G_PREFETCH(stage, k0_)  do {                                              \
        uint32_t dstb = sbase + (uint32_t)(stage) * O_STAGE_B;                        \
        _Pragma("unroll")                                                             \
        for (int t = 0; t < 2; t++) {                                                 \
            int row = ld_row + t * 64;                                                \
            uint32_t so = (uint32_t)(row * LDT + ld_s * 8) * 2;                       \
            CP16(dstb + so,             A  + (size_t)(m0 + row) * K + (k0_) + ld_s * 8); \
            CP16(dstb + G_TILE_B + so,  BT + (size_t)(n0 + row) * K + (k0_) + ld_s * 8); \
        }                                                                             \
        CP_COMMIT();                                                                  \
    } while (0)

    G_PREFETCH(0, 0);

    for (int c = 0; c < nchunks; c++) {
        CP_WAIT0();
        __syncthreads();
        if (c + 1 < nchunks) G_PREFETCH((c + 1) & 1, (c + 1) * KC);

        const uint32_t sb = sbase + (uint32_t)(c & 1) * O_STAGE_B;
        const uint32_t sA = sb, sB = sb + G_TILE_B;

        #pragma unroll
        for (int ks = 0; ks < 2; ks++) {
            uint32_t ah[4][4], bh[4][2];
            #pragma unroll
            for (int i = 0; i < 4; i++) {
                uint32_t off = (uint32_t)((a_row + i * 16) * LDT + ks * 16 + a_kof) * 2;
                ldmatrix_x4(ah[i][0], ah[i][1], ah[i][2], ah[i][3], sA + off);
            }
            #pragma unroll
            for (int j2 = 0; j2 < 4; j2 += 2) {
                uint32_t off = (uint32_t)((b_row4 + j2 * 8) * LDT + ks * 16 + b_kof4) * 2;
                ldmatrix_x4(bh[j2][0], bh[j2][1], bh[j2+1][0], bh[j2+1][1], sB + off);
            }
            #pragma unroll
            for (int i = 0; i < 4; i++)
                #pragma unroll
                for (int j = 0; j < 4; j++)
                    mma_f16(acc[i][j], ah[i], bh[j]);
        }
    }

    __syncthreads();
    const int grp = lane >> 2, tg = lane & 3;
    #pragma unroll
    for (int i = 0; i < 4; i++) {
        int row0 = m0 + warp_m * 64 + i * 16 + grp;
        #pragma unroll
        for (int j = 0; j < 4; j++) {
            int col = n0 + warp_n * 32 + j * 8 + tg * 2;
            float b0 = bias[col], b1 = bias[col + 1];
            float* p0 = Cf + (size_t)row0 * N + col;
            p0[0] = acc[i][j][0] + b0;
            p0[1] = acc[i][j][1] + b1;
            float* p1 = Cf + (size_t)(row0 + 8) * N + col;
            p1[0] = acc[i][j][2] + b0;
            p1[1] = acc[i][j][3] + b1;
        }
    }
    #undef G_PREFETCH
}

// ---------------------------------------------------------------------------
// fp16 HMMA causal flash attention, v9: QK 2-term, PV 1-term, plain ctx out.
// ---------------------------------------------------------------------------
#define A_TILE_B 8192                      // 64 rows * 128 B
#define A_STAGE_B (2 * A_TILE_B)           // 16384 B (K + V)
#define SMEM_ATTN (2 * A_STAGE_B)          // 32768 B

__global__ void __launch_bounds__(128, 3) attn_hmma(
    const __half* __restrict__ Qhi, const __half* __restrict__ Qlo,
    const __half* __restrict__ Kh, const __half* __restrict__ Vh,
    uint32_t* __restrict__ Ctx2) {
    extern __shared__ __half smA[];
    const uint32_t sbase = smem_u32(smA);

    const int tid  = threadIdx.x;
    const int wid  = tid >> 5;
    const int lane = tid & 31;
    const int grp  = lane >> 2, tg = lane & 3;
    const int qt = (int)gridDim.x - 1 - (int)blockIdx.x;   // heavy tiles first
    const int h  = blockIdx.y;
    const int b  = blockIdx.z;
    const int q0 = qt * 64;

    const int a_row = wid * 16 + ((lane >> 3) & 1) * 8 + (lane & 7);
    const int a_kby = (((lane >> 4) & 1) * 8) * 2;
    const int k_row4 = (lane >> 4) * 8 + (lane & 7);
    const int k_kby4 = (((lane >> 3) & 1) * 8) * 2;
    const int v_row4 = ((lane >> 3) & 1) * 8 + (lane & 7);
    const int v_cby4 = ((lane >> 4) * 8) * 2;

    // --- stage Q hi/lo through stage area (swizzled), preload frags ---
    #pragma unroll
    for (int t = 0; t < 4; t++) {
        int idx = tid + t * 128;
        int r = idx >> 3, s = idx & 7;
        size_t g = (size_t)(b * SS + q0 + r) * DD + h * HD + s * 8;
        uint32_t so = SWZ(r * 128 + s * 16);
        *(uint4*)((char*)smA + so) = *(const uint4*)(Qhi + g);
        *(uint4*)((char*)smA + A_TILE_B + so) = *(const uint4*)(Qlo + g);
    }
    __syncthreads();
    uint32_t qh[4][4], ql[4][4];
    #pragma unroll
    for (int ks = 0; ks < 4; ks++) {
        uint32_t off = SWZ(a_row * 128 + ks * 32 + a_kby);
        ldmatrix_x4(qh[ks][0], qh[ks][1], qh[ks][2], qh[ks][3], sbase + off);
        ldmatrix_x4(ql[ks][0], ql[ks][1], ql[ks][2], ql[ks][3], sbase + A_TILE_B + off);
    }
    __syncthreads();

    #define A_PREFETCH(stage, k0_)  do {                                              \
        uint32_t dstb = sbase + (uint32_t)(stage) * A_STAGE_B;                        \
        _Pragma("unroll")                                                             \
        for (int t = 0; t < 4; t++) {                                                 \
            int idx = tid + t * 128;                                                  \
            int r = idx >> 3, s = idx & 7;                                            \
            size_t g = (size_t)(b * SS + (k0_) + r) * DD + h * HD + s * 8;            \
            uint32_t so = SWZ(r * 128 + s * 16);                                      \
            CP16(dstb + so,              Kh + g);                                     \
            CP16(dstb + A_TILE_B + so,   Vh + g);                                     \
        }                                                                             \
        CP_COMMIT();                                                                  \
    } while (0)

    A_PREFETCH(0, 0);

    float m0 = -INFINITY, m1 = -INFINITY, l0 = 0.f, l1 = 0.f;
    float o[8][4];
    #pragma unroll
    for (int j = 0; j < 8; j++)
        #pragma unroll
        for (int e = 0; e < 4; e++) o[j][e] = 0.f;

    for (int kt = 0; kt <= qt; kt++) {
        CP_WAIT0();
        __syncthreads();
        if (kt < qt) A_PREFETCH((kt + 1) & 1, (kt + 1) * 64);

        const uint32_t sb = sbase + (uint32_t)(kt & 1) * A_STAGE_B;
        const uint32_t sKh_u = sb, sVh_u = sb + A_TILE_B;

        // --- S = Q K^T (2-term: Qh*K + Ql*K) ---
        float sc[8][4];
        #pragma unroll
        for (int j = 0; j < 8; j++)
            #pragma unroll
            for (int e = 0; e < 4; e++) sc[j][e] = 0.f;

        #pragma unroll
        for (int ks = 0; ks < 4; ks++) {
            uint32_t kb[8][2];
            #pragma unroll
            for (int j2 = 0; j2 < 8; j2 += 2) {
                uint32_t off = SWZ((j2 * 8 + k_row4) * 128 + ks * 32 + k_kby4);
                ldmatrix_x4(kb[j2][0], kb[j2][1], kb[j2+1][0], kb[j2+1][1], sKh_u + off);
            }
            #pragma unroll
            for (int j = 0; j < 8; j++) mma_f16(sc[j], qh[ks], kb[j]);
            #pragma unroll
            for (int j = 0; j < 8; j++) mma_f16(sc[j], ql[ks], kb[j]);
        }

        // --- causal mask on diagonal tile ---
        if (kt == qt) {
            const int qr0 = wid * 16 + grp;
            #pragma unroll
            for (int j = 0; j < 8; j++) {
                int kc = j * 8 + 2 * tg;
                if (kc     > qr0)     sc[j][0] = -INFINITY;
                if (kc + 1 > qr0)     sc[j][1] = -INFINITY;
                if (kc     > qr0 + 8) sc[j][2] = -INFINITY;
                if (kc + 1 > qr0 + 8) sc[j][3] = -INFINITY;
            }
        }

        // --- online softmax in exp2 domain, raw ex2.approx ---
        float mx0 = -INFINITY, mx1 = -INFINITY;
        #pragma unroll
        for (int j = 0; j < 8; j++) {
            mx0 = fmaxf(mx0, fmaxf(sc[j][0], sc[j][1]));
            mx1 = fmaxf(mx1, fmaxf(sc[j][2], sc[j][3]));
        }
        mx0 = fmaxf(mx0, __shfl_xor_sync(0xffffffffu, mx0, 1));
        mx0 = fmaxf(mx0, __shfl_xor_sync(0xffffffffu, mx0, 2));
        mx1 = fmaxf(mx1, __shfl_xor_sync(0xffffffffu, mx1, 1));
        mx1 = fmaxf(mx1, __shfl_xor_sync(0xffffffffu, mx1, 2));
        float mn0 = fmaxf(m0, mx0), mn1 = fmaxf(m1, mx1);
        float al0 = ex2(m0 - mn0), al1 = ex2(m1 - mn1);
        float s0 = 0.f, s1 = 0.f;
        #pragma unroll
        for (int j = 0; j < 8; j++) {
            sc[j][0] = ex2(sc[j][0] - mn0);
            sc[j][1] = ex2(sc[j][1] - mn0);
            sc[j][2] = ex2(sc[j][2] - mn1);
            sc[j][3] = ex2(sc[j][3] - mn1);
            s0 += sc[j][0] + sc[j][1];
            s1 += sc[j][2] + sc[j][3];
        }
        s0 += __shfl_xor_sync(0xffffffffu, s0, 1);
        s0 += __shfl_xor_sync(0xffffffffu, s0, 2);
        s1 += __shfl_xor_sync(0xffffffffu, s1, 1);
        s1 += __shfl_xor_sync(0xffffffffu, s1, 2);
        l0 = l0 * al0 + s0;  m0 = mn0;
        l1 = l1 * al1 + s1;  m1 = mn1;
        #pragma unroll
        for (int j = 0; j < 8; j++) {
            o[j][0] *= al0; o[j][1] *= al0;
            o[j][2] *= al1; o[j][3] *= al1;
        }

        // --- O += P V (1-term: P rounding is below downstream fp16 floor) ---
        #pragma unroll
        for (int ks = 0; ks < 4; ks++) {
            uint32_t ph[4];
            ph[0] = pack_h2(sc[2*ks][0],   sc[2*ks][1]);
            ph[1] = pack_h2(sc[2*ks][2],   sc[2*ks][3]);
            ph[2] = pack_h2(sc[2*ks+1][0], sc[2*ks+1][1]);
            ph[3] = pack_h2(sc[2*ks+1][2], sc[2*ks+1][3]);
            uint32_t vb[8][2];
            #pragma unroll
            for (int j2 = 0; j2 < 8; j2 += 2) {
                uint32_t off = SWZ((ks * 16 + v_row4) * 128 + j2 * 16 + v_cby4);
                ldmatrix_x4_trans(vb[j2][0], vb[j2][1], vb[j2+1][0], vb[j2+1][1], sVh_u + off);
            }
            #pragma unroll
            for (int j2 = 0; j2 < 8; j2++) mma_f16(o[j2], ph, vb[j2]);
        }
    }

    // --- epilogue: ctx = O / l, plain fp16 ---
    const float inv0 = 1.f / l0, inv1 = 1.f / l1;
    const int row0 = b * SS + q0 + wid * 16 + grp;
    #pragma unroll
    for (int j2 = 0; j2 < 8; j2++) {
        const int cidx = h * 32 + j2 * 4 + tg;    // f16x2 units
        Ctx2[(size_t)row0 * (DD / 2) + cidx] = pack_h2(o[j2][0] * inv0, o[j2][1] * inv0);
        Ctx2[(size_t)(row0 + 8) * (DD / 2) + cidx] = pack_h2(o[j2][2] * inv1, o[j2][3] * inv1);
    }
    #undef A_PREFETCH
}

// ---------------------------------------------------------------------------
extern "C" void kernel_launch(void* const* d_in, const int* in_sizes, int n_in,
                              void* d_out, int out_size) {
    const float* x  = (const float*)d_in[0];
    const float* Wq = (const float*)d_in[1];
    const float* bq = (const float*)d_in[2];
    const float* Wk = (const float*)d_in[3];
    const float* bk = (const float*)d_in[4];
    const float* Wv = (const float*)d_in[5];
    const float* bv = (const float*)d_in[6];
    const float* Wo = (const float*)d_in[7];
    const float* bo = (const float*)d_in[8];
    float* out = (float*)d_out;

    __half *xhi, *xlo, *ctx, *qhi, *qlo, *kh, *vh;
    cudaGetSymbolAddress((void**)&xhi, g_xhi);
    cudaGetSymbolAddress((void**)&xlo, g_xlo);
    cudaGetSymbolAddress((void**)&ctx, g_ctx);
    cudaGetSymbolAddress((void**)&qhi, g_qhi);
    cudaGetSymbolAddress((void**)&qlo, g_qlo);
    cudaGetSymbolAddress((void**)&kh, g_kh);
    cudaGetSymbolAddress((void**)&vh, g_vh);
    __half *wqT, *wkT, *wvT, *woT;
    cudaGetSymbolAddress((void**)&wqT, g_wqT);
    cudaGetSymbolAddress((void**)&wkT, g_wkT);
    cudaGetSymbolAddress((void**)&wvT, g_wvT);
    cudaGetSymbolAddress((void**)&woT, g_woT);

    // 1) input conversions
    int n4 = M_TOT * DD / 4;
    cvt_split4<<<(n4 + 255) / 256, 256>>>((const float4*)x,
                                          (uint32_t*)xhi, (uint32_t*)xlo, n4);
    WJob jq{Wq, wqT}, jk{Wk, wkT}, jv{Wv, wvT}, jo{Wo, woT};
    cvt_wT4<<<dim3(DD / 32, DD / 32, 4), dim3(32, 8)>>>(jq, jk, jv, jo);

    // 2) fused QKV projection (Q 2-term split output; K/V 1-term plain)
    cudaFuncSetAttribute(gemm_qkv, cudaFuncAttributeMaxDynamicSharedMemorySize, SMEM_GEMM);
    cudaFuncSetAttribute(gemm_hmma, cudaFuncAttributeMaxDynamicSharedMemorySize, SMEM_OPROJ);
    QKVJob job;
    job.bT[0] = wqT; job.bias[0] = bq;
    job.chi[0] = (uint32_t*)qhi; job.clo[0] = (uint32_t*)qlo;
    job.scale[0] = 0.125f * 1.44269504f;
    job.bT[1] = wkT; job.bias[1] = bk;
    job.chi[1] = (uint32_t*)kh; job.clo[1] = nullptr;
    job.scale[1] = 1.0f;
    job.bT[2] = wvT; job.bias[2] = bv;
    job.chi[2] = (uint32_t*)vh; job.clo[2] = nullptr;
    job.scale[2] = 1.0f;
    dim3 gq(3 * DD / CTA_N, M_TOT / CTA_M);   // (24, 32) = 768 CTAs
    gemm_qkv<<<gq, 256, SMEM_GEMM>>>(xhi, xlo, job, M_TOT, DD, DD);

    // 3) attention -> ctx plain fp16
    cudaFuncSetAttribute(attn_hmma, cudaFuncAttributeMaxDynamicSharedMemorySize, SMEM_ATTN);
    attn_hmma<<<dim3(SS / 64, HH, BB), 128, SMEM_ATTN>>>(
        qhi, qlo, kh, vh, (uint32_t*)ctx);

    // 4) output projection (1-term) -> fp32 out
    dim3 gg(DD / CTA_N, M_TOT / CTA_M);
    gemm_hmma<<<gg, 256, SMEM_OPROJ>>>(ctx, woT, bo, out, M_TOT, DD, DD);
}

// round 17
// speedup vs baseline: 2.4592x; 1.2958x over previous
#include <cuda_runtime.h>
#include <cuda_fp16.h>
#include <cstdint>
#include <math.h>

#define BB 2
#define SS 2048
#define DD 1024
#define HH 16
#define HD 64
#define M_TOT (BB*SS)   // 4096

// ---------------------------------------------------------------------------
// Scratch (__device__ globals: allocation-free per harness rules)
// All operands plain fp16 (1-term everywhere; error budget verified).
// ---------------------------------------------------------------------------
__device__ __half g_xh[M_TOT * DD];
__device__ __half g_ctx[M_TOT * DD];

__device__ __half g_qh[M_TOT * DD];
__device__ __half g_kh[M_TOT * DD];
__device__ __half g_vh[M_TOT * DD];

__device__ __half g_wqT[DD * DD];
__device__ __half g_wkT[DD * DD];
__device__ __half g_wvT[DD * DD];
__device__ __half g_woT[DD * DD];

// ---------------------------------------------------------------------------
// helpers
// ---------------------------------------------------------------------------
__device__ __forceinline__ uint32_t smem_u32(const void* p) {
    uint32_t a;
    asm("{ .reg .u64 t; cvta.to.shared.u64 t, %1; cvt.u32.u64 %0, t; }" : "=r"(a) : "l"(p));
    return a;
}
__device__ __forceinline__ void ldmatrix_x4(uint32_t& r0, uint32_t& r1, uint32_t& r2,
                                            uint32_t& r3, uint32_t addr) {
    asm volatile("ldmatrix.sync.aligned.m8n8.x4.shared.b16 {%0,%1,%2,%3}, [%4];"
                 : "=r"(r0), "=r"(r1), "=r"(r2), "=r"(r3) : "r"(addr));
}
__device__ __forceinline__ void ldmatrix_x4_trans(uint32_t& r0, uint32_t& r1, uint32_t& r2,
                                                  uint32_t& r3, uint32_t addr) {
    asm volatile("ldmatrix.sync.aligned.m8n8.x4.trans.shared.b16 {%0,%1,%2,%3}, [%4];"
                 : "=r"(r0), "=r"(r1), "=r"(r2), "=r"(r3) : "r"(addr));
}
__device__ __forceinline__ void mma_f16(float* d, const uint32_t* a, const uint32_t* b) {
    asm volatile(
        "mma.sync.aligned.m16n8k16.row.col.f32.f16.f16.f32 "
        "{%0,%1,%2,%3}, {%4,%5,%6,%7}, {%8,%9}, {%0,%1,%2,%3};"
        : "+f"(d[0]), "+f"(d[1]), "+f"(d[2]), "+f"(d[3])
        : "r"(a[0]), "r"(a[1]), "r"(a[2]), "r"(a[3]), "r"(b[0]), "r"(b[1]));
}
// fast raw exp2 (args <= 0, bounded; -inf -> 0)
__device__ __forceinline__ float ex2(float x) {
    float r;
    asm("ex2.approx.ftz.f32 %0, %1;" : "=f"(r) : "f"(x));
    return r;
}
__device__ __forceinline__ uint32_t pack_h2(float x, float y) {
    __half2 h = __floats2half2_rn(x, y);
    return *reinterpret_cast<uint32_t*>(&h);
}
#define CP16(d, s) asm volatile("cp.async.cg.shared.global [%0], [%1], 16;" :: "r"(d), "l"(s))
#define CP_COMMIT() asm volatile("cp.async.commit_group;" ::: "memory")
#define CP_WAIT0()  asm volatile("cp.async.wait_group 0;" ::: "memory")
// SW128 swizzle (1024B atoms)
#define SWZ(b) ((uint32_t)(b) ^ ((((uint32_t)(b)) >> 3) & 0x70u))

// ---------------------------------------------------------------------------
// fp32 -> plain fp16 (elementwise, vectorized)
// ---------------------------------------------------------------------------
__global__ void cvt4(const float4* __restrict__ in, uint32_t* __restrict__ o, int n4) {
    int i = blockIdx.x * blockDim.x + threadIdx.x;
    if (i >= n4) return;
    float4 v = in[i];
    o[2*i]   = pack_h2(v.x, v.y);
    o[2*i+1] = pack_h2(v.z, v.w);
}

// ---------------------------------------------------------------------------
// W[K][N] fp32 -> transposed plain fp16 [N][K]; 4 weights in one launch
// ---------------------------------------------------------------------------
struct WJob { const float* W; __half* hT; };

__global__ void cvt_wT4(WJob j0, WJob j1, WJob j2, WJob j3) {
    __shared__ float t[32][33];
    WJob j = (blockIdx.z == 0) ? j0 : (blockIdx.z == 1) ? j1 : (blockIdx.z == 2) ? j2 : j3;
    int n0 = blockIdx.x * 32, k0 = blockIdx.y * 32;
    int tx = threadIdx.x, ty = threadIdx.y;
    #pragma unroll
    for (int r = 0; r < 32; r += 8)
        t[ty + r][tx] = j.W[(size_t)(k0 + ty + r) * DD + n0 + tx];
    __syncthreads();
    #pragma unroll
    for (int r = 0; r < 32; r += 8) {
        float v = t[tx][ty + r];
        j.hT[(size_t)(n0 + ty + r) * DD + k0 + tx] = __float2half_rn(v);
    }
}

// ---------------------------------------------------------------------------
// GEMM geometry: 1-term -> 2 tiles/stage
// ---------------------------------------------------------------------------
#define CTA_M 128
#define CTA_N 128
#define KC 32
#define LDT 40
#define G_TILE_B (128 * LDT * 2)           // 10240 B
#define G_STAGE_B (2 * G_TILE_B)           // 20480 B
#define SMEM_GEMM (2 * G_STAGE_B)          // 40960 B

// ---------------------------------------------------------------------------
// Fused QKV GEMM: proj = blockIdx.x / 8, all 1-term, plain fp16 output.
// ---------------------------------------------------------------------------
struct QKVJob {
    const __half* bT[3];
    const float*  bias[3];
    uint32_t*     out[3];
    float         scale[3];
};

__global__ void __launch_bounds__(256, 2) gemm_qkv(
    const __half* __restrict__ A, QKVJob job, int M, int N, int K) {
    extern __shared__ __half smG[];
    const uint32_t sbase = smem_u32(smG);

    const int proj = blockIdx.x >> 3;
    const __half* __restrict__ BT = job.bT[proj];
    const float* __restrict__ bias = job.bias[proj];
    uint32_t* __restrict__ Out2 = job.out[proj];
    const float scale = job.scale[proj];

    const int tid  = threadIdx.x;
    const int wid  = tid >> 5;
    const int lane = tid & 31;
    const int warp_m = wid & 1;
    const int warp_n = wid >> 1;
    const int m0 = blockIdx.y * CTA_M;
    const int n0 = (blockIdx.x & 7) * CTA_N;

    float acc[4][4][4];
    #pragma unroll
    for (int i = 0; i < 4; i++)
        #pragma unroll
        for (int j = 0; j < 4; j++)
            #pragma unroll
            for (int e = 0; e < 4; e++) acc[i][j][e] = 0.f;

    const int lm_r  = lane & 7;
    const int lm_m4 = lane >> 3;
    const int a_row = warp_m * 64 + (lm_m4 & 1) * 8 + lm_r;
    const int a_kof = (lm_m4 >> 1) * 8;
    const int b_row4 = warp_n * 32 + (lane >> 4) * 8 + lm_r;
    const int b_kof4 = ((lane >> 3) & 1) * 8;

    const int ld_row = tid >> 2, ld_s = tid & 3;
    const int nchunks = K / KC;

    #define G_PREFETCH(stage, k0_)  do {                                              \
        uint32_t dstb = sbase + (uint32_t)(stage) * G_STAGE_B;                        \
        _Pragma("unroll")                                                             \
        for (int t = 0; t < 2; t++) {                                                 \
            int row = ld_row + t * 64;                                                \
            uint32_t so = (uint32_t)(row * LDT + ld_s * 8) * 2;                       \
            CP16(dstb + so,             A  + (size_t)(m0 + row) * K + (k0_) + ld_s * 8); \
            CP16(dstb + G_TILE_B + so,  BT + (size_t)(n0 + row) * K + (k0_) + ld_s * 8); \
        }                                                                             \
        CP_COMMIT();                                                                  \
    } while (0)

    G_PREFETCH(0, 0);

    for (int c = 0; c < nchunks; c++) {
        CP_WAIT0();
        __syncthreads();
        if (c + 1 < nchunks) G_PREFETCH((c + 1) & 1, (c + 1) * KC);

        const uint32_t sb = sbase + (uint32_t)(c & 1) * G_STAGE_B;
        const uint32_t sA = sb, sB = sb + G_TILE_B;

        #pragma unroll
        for (int ks = 0; ks < 2; ks++) {
            uint32_t ah[4][4], bh[4][2];
            #pragma unroll
            for (int i = 0; i < 4; i++) {
                uint32_t off = (uint32_t)((a_row + i * 16) * LDT + ks * 16 + a_kof) * 2;
                ldmatrix_x4(ah[i][0], ah[i][1], ah[i][2], ah[i][3], sA + off);
            }
            #pragma unroll
            for (int j2 = 0; j2 < 4; j2 += 2) {
                uint32_t off = (uint32_t)((b_row4 + j2 * 8) * LDT + ks * 16 + b_kof4) * 2;
                ldmatrix_x4(bh[j2][0], bh[j2][1], bh[j2+1][0], bh[j2+1][1], sB + off);
            }
            #pragma unroll
            for (int i = 0; i < 4; i++)
                #pragma unroll
                for (int j = 0; j < 4; j++)
                    mma_f16(acc[i][j], ah[i], bh[j]);
        }
    }

    __syncthreads();
    const int grp = lane >> 2, tg = lane & 3;
    #pragma unroll
    for (int i = 0; i < 4; i++) {
        int row0 = m0 + warp_m * 64 + i * 16 + grp;
        #pragma unroll
        for (int j = 0; j < 4; j++) {
            int col = n0 + warp_n * 32 + j * 8 + tg * 2;
            float b0 = bias[col], b1 = bias[col + 1];
            Out2[(size_t)row0 * (N / 2) + col / 2] =
                pack_h2((acc[i][j][0] + b0) * scale, (acc[i][j][1] + b1) * scale);
            Out2[(size_t)(row0 + 8) * (N / 2) + col / 2] =
                pack_h2((acc[i][j][2] + b0) * scale, (acc[i][j][3] + b1) * scale);
        }
    }
    #undef G_PREFETCH
}

// ---------------------------------------------------------------------------
// Out-projection GEMM: ctx fp16 @ WoT fp16 -> fp32 out (1-term)
// ---------------------------------------------------------------------------
__global__ void __launch_bounds__(256, 2) gemm_hmma(
    const __half* __restrict__ A, const __half* __restrict__ BT,
    const float* __restrict__ bias, float* __restrict__ Cf,
    int M, int N, int K) {
    extern __shared__ __half smG[];
    const uint32_t sbase = smem_u32(smG);

    const int tid  = threadIdx.x;
    const int wid  = tid >> 5;
    const int lane = tid & 31;
    const int warp_m = wid & 1;
    const int warp_n = wid >> 1;
    const int m0 = blockIdx.y * CTA_M;
    const int n0 = blockIdx.x * CTA_N;

    float acc[4][4][4];
    #pragma unroll
    for (int i = 0; i < 4; i++)
        #pragma unroll
        for (int j = 0; j < 4; j++)
            #pragma unroll
            for (int e = 0; e < 4; e++) acc[i][j][e] = 0.f;

    const int lm_r  = lane & 7;
    const int lm_m4 = lane >> 3;
    const int a_row = warp_m * 64 + (lm_m4 & 1) * 8 + lm_r;
    const int a_kof = (lm_m4 >> 1) * 8;
    const int b_row4 = warp_n * 32 + (lane >> 4) * 8 + lm_r;
    const int b_kof4 = ((lane >> 3) & 1) * 8;

    const int ld_row = tid >> 2, ld_s = tid & 3;
    const int nchunks = K / KC;

    #define G_PREFETCH(stage, k0_)  do {                                              \
        uint32_t dstb = sbase + (uint32_t)(stage) * G_STAGE_B;                        \
        _Pragma("unroll")                                                             \
        for (int t = 0; t < 2; t++) {                                                 \
            int row = ld_row + t * 64;                                                \
            uint32_t so = (uint32_t)(row * LDT + ld_s * 8) * 2;                       \
            CP16(dstb + so,             A  + (size_t)(m0 + row) * K + (k0_) + ld_s * 8); \
            CP16(dstb + G_TILE_B + so,  BT + (size_t)(n0 + row) * K + (k0_) + ld_s * 8); \
        }                                                                             \
        CP_COMMIT();                                                                  \
    } while (0)

    G_PREFETCH(0, 0);

    for (int c = 0; c < nchunks; c++) {
        CP_WAIT0();
        __syncthreads();
        if (c + 1 < nchunks) G_PREFETCH((c + 1) & 1, (c + 1) * KC);

        const uint32_t sb = sbase + (uint32_t)(c & 1) * G_STAGE_B;
        const uint32_t sA = sb, sB = sb + G_TILE_B;

        #pragma unroll
        for (int ks = 0; ks < 2; ks++) {
            uint32_t ah[4][4], bh[4][2];
            #pragma unroll
            for (int i = 0; i < 4; i++) {
                uint32_t off = (uint32_t)((a_row + i * 16) * LDT + ks * 16 + a_kof) * 2;
                ldmatrix_x4(ah[i][0], ah[i][1], ah[i][2], ah[i][3], sA + off);
            }
            #pragma unroll
            for (int j2 = 0; j2 < 4; j2 += 2) {
                uint32_t off = (uint32_t)((b_row4 + j2 * 8) * LDT + ks * 16 + b_kof4) * 2;
                ldmatrix_x4(bh[j2][0], bh[j2][1], bh[j2+1][0], bh[j2+1][1], sB + off);
            }
            #pragma unroll
            for (int i = 0; i < 4; i++)
                #pragma unroll
                for (int j = 0; j < 4; j++)
                    mma_f16(acc[i][j], ah[i], bh[j]);
        }
    }

    __syncthreads();
    const int grp = lane >> 2, tg = lane & 3;
    #pragma unroll
    for (int i = 0; i < 4; i++) {
        int row0 = m0 + warp_m * 64 + i * 16 + grp;
        #pragma unroll
        for (int j = 0; j < 4; j++) {
            int col = n0 + warp_n * 32 + j * 8 + tg * 2;
            float b0 = bias[col], b1 = bias[col + 1];
            float* p0 = Cf + (size_t)row0 * N + col;
            p0[0] = acc[i][j][0] + b0;
            p0[1] = acc[i][j][1] + b1;
            float* p1 = Cf + (size_t)(row0 + 8) * N + col;
            p1[0] = acc[i][j][2] + b0;
            p1[1] = acc[i][j][3] + b1;
        }
    }
    #undef G_PREFETCH
}

// ---------------------------------------------------------------------------
// fp16 HMMA causal flash attention, v10: fully 1-term (QK and PV).
// ---------------------------------------------------------------------------
#define A_TILE_B 8192                      // 64 rows * 128 B
#define A_STAGE_B (2 * A_TILE_B)           // 16384 B (K + V)
#define SMEM_ATTN (2 * A_STAGE_B)          // 32768 B

__global__ void __launch_bounds__(128, 3) attn_hmma(
    const __half* __restrict__ Qh, const __half* __restrict__ Kh,
    const __half* __restrict__ Vh, uint32_t* __restrict__ Ctx2) {
    extern __shared__ __half smA[];
    const uint32_t sbase = smem_u32(smA);

    const int tid  = threadIdx.x;
    const int wid  = tid >> 5;
    const int lane = tid & 31;
    const int grp  = lane >> 2, tg = lane & 3;
    const int qt = (int)gridDim.x - 1 - (int)blockIdx.x;   // heavy tiles first
    const int h  = blockIdx.y;
    const int b  = blockIdx.z;
    const int q0 = qt * 64;

    const int a_row = wid * 16 + ((lane >> 3) & 1) * 8 + (lane & 7);
    const int a_kby = (((lane >> 4) & 1) * 8) * 2;
    const int k_row4 = (lane >> 4) * 8 + (lane & 7);
    const int k_kby4 = (((lane >> 3) & 1) * 8) * 2;
    const int v_row4 = ((lane >> 3) & 1) * 8 + (lane & 7);
    const int v_cby4 = ((lane >> 4) * 8) * 2;

    // --- stage Q through stage-0 smem (swizzled), preload frags ---
    #pragma unroll
    for (int t = 0; t < 4; t++) {
        int idx = tid + t * 128;
        int r = idx >> 3, s = idx & 7;
        size_t g = (size_t)(b * SS + q0 + r) * DD + h * HD + s * 8;
        uint32_t so = SWZ(r * 128 + s * 16);
        *(uint4*)((char*)smA + so) = *(const uint4*)(Qh + g);
    }
    __syncthreads();
    uint32_t qh[4][4];
    #pragma unroll
    for (int ks = 0; ks < 4; ks++) {
        uint32_t off = SWZ(a_row * 128 + ks * 32 + a_kby);
        ldmatrix_x4(qh[ks][0], qh[ks][1], qh[ks][2], qh[ks][3], sbase + off);
    }
    __syncthreads();

    #define A_PREFETCH(stage, k0_)  do {                                              \
        uint32_t dstb = sbase + (uint32_t)(stage) * A_STAGE_B;                        \
        _Pragma("unroll")                                                             \
        for (int t = 0; t < 4; t++) {                                                 \
            int idx = tid + t * 128;                                                  \
            int r = idx >> 3, s = idx & 7;                                            \
            size_t g = (size_t)(b * SS + (k0_) + r) * DD + h * HD + s * 8;            \
            uint32_t so = SWZ(r * 128 + s * 16);                                      \
            CP16(dstb + so,              Kh + g);                                     \
            CP16(dstb + A_TILE_B + so,   Vh + g);                                     \
        }                                                                             \
        CP_COMMIT();                                                                  \
    } while (0)

    A_PREFETCH(0, 0);

    float m0 = -INFINITY, m1 = -INFINITY, l0 = 0.f, l1 = 0.f;
    float o[8][4];
    #pragma unroll
    for (int j = 0; j < 8; j++)
        #pragma unroll
        for (int e = 0; e < 4; e++) o[j][e] = 0.f;

    for (int kt = 0; kt <= qt; kt++) {
        CP_WAIT0();
        __syncthreads();
        if (kt < qt) A_PREFETCH((kt + 1) & 1, (kt + 1) * 64);

        const uint32_t sb = sbase + (uint32_t)(kt & 1) * A_STAGE_B;
        const uint32_t sKh_u = sb, sVh_u = sb + A_TILE_B;

        // --- S = Q K^T (1-term) ---
        float sc[8][4];
        #pragma unroll
        for (int j = 0; j < 8; j++)
            #pragma unroll
            for (int e = 0; e < 4; e++) sc[j][e] = 0.f;

        #pragma unroll
        for (int ks = 0; ks < 4; ks++) {
            uint32_t kb[8][2];
            #pragma unroll
            for (int j2 = 0; j2 < 8; j2 += 2) {
                uint32_t off = SWZ((j2 * 8 + k_row4) * 128 + ks * 32 + k_kby4);
                ldmatrix_x4(kb[j2][0], kb[j2][1], kb[j2+1][0], kb[j2+1][1], sKh_u + off);
            }
            #pragma unroll
            for (int j = 0; j < 8; j++) mma_f16(sc[j], qh[ks], kb[j]);
        }

        // --- causal mask on diagonal tile ---
        if (kt == qt) {
            const int qr0 = wid * 16 + grp;
            #pragma unroll
            for (int j = 0; j < 8; j++) {
                int kc = j * 8 + 2 * tg;
                if (kc     > qr0)     sc[j][0] = -INFINITY;
                if (kc + 1 > qr0)     sc[j][1] = -INFINITY;
                if (kc     > qr0 + 8) sc[j][2] = -INFINITY;
                if (kc + 1 > qr0 + 8) sc[j][3] = -INFINITY;
            }
        }

        // --- online softmax in exp2 domain, raw ex2.approx ---
        float mx0 = -INFINITY, mx1 = -INFINITY;
        #pragma unroll
        for (int j = 0; j < 8; j++) {
            mx0 = fmaxf(mx0, fmaxf(sc[j][0], sc[j][1]));
            mx1 = fmaxf(mx1, fmaxf(sc[j][2], sc[j][3]));
        }
        mx0 = fmaxf(mx0, __shfl_xor_sync(0xffffffffu, mx0, 1));
        mx0 = fmaxf(mx0, __shfl_xor_sync(0xffffffffu, mx0, 2));
        mx1 = fmaxf(mx1, __shfl_xor_sync(0xffffffffu, mx1, 1));
        mx1 = fmaxf(mx1, __shfl_xor_sync(0xffffffffu, mx1, 2));
        float mn0 = fmaxf(m0, mx0), mn1 = fmaxf(m1, mx1);
        float al0 = ex2(m0 - mn0), al1 = ex2(m1 - mn1);
        float s0 = 0.f, s1 = 0.f;
        #pragma unroll
        for (int j = 0; j < 8; j++) {
            sc[j][0] = ex2(sc[j][0] - mn0);
            sc[j][1] = ex2(sc[j][1] - mn0);
            sc[j][2] = ex2(sc[j][2] - mn1);
            sc[j][3] = ex2(sc[j][3] - mn1);
            s0 += sc[j][0] + sc[j][1];
            s1 += sc[j][2] + sc[j][3];
        }
        s0 += __shfl_xor_sync(0xffffffffu, s0, 1);
        s0 += __shfl_xor_sync(0xffffffffu, s0, 2);
        s1 += __shfl_xor_sync(0xffffffffu, s1, 1);
        s1 += __shfl_xor_sync(0xffffffffu, s1, 2);
        l0 = l0 * al0 + s0;  m0 = mn0;
        l1 = l1 * al1 + s1;  m1 = mn1;
        #pragma unroll
        for (int j = 0; j < 8; j++) {
            o[j][0] *= al0; o[j][1] *= al0;
            o[j][2] *= al1; o[j][3] *= al1;
        }

        // --- O += P V (1-term) ---
        #pragma unroll
        for (int ks = 0; ks < 4; ks++) {
            uint32_t ph[4];
            ph[0] = pack_h2(sc[2*ks][0],   sc[2*ks][1]);
            ph[1] = pack_h2(sc[2*ks][2],   sc[2*ks][3]);
            ph[2] = pack_h2(sc[2*ks+1][0], sc[2*ks+1][1]);
            ph[3] = pack_h2(sc[2*ks+1][2], sc[2*ks+1][3]);
            uint32_t vb[8][2];
            #pragma unroll
            for (int j2 = 0; j2 < 8; j2 += 2) {
                uint32_t off = SWZ((ks * 16 + v_row4) * 128 + j2 * 16 + v_cby4);
                ldmatrix_x4_trans(vb[j2][0], vb[j2][1], vb[j2+1][0], vb[j2+1][1], sVh_u + off);
            }
            #pragma unroll
            for (int j2 = 0; j2 < 8; j2++) mma_f16(o[j2], ph, vb[j2]);
        }
    }

    // --- epilogue: ctx = O / l, plain fp16 ---
    const float inv0 = 1.f / l0, inv1 = 1.f / l1;
    const int row0 = b * SS + q0 + wid * 16 + grp;
    #pragma unroll
    for (int j2 = 0; j2 < 8; j2++) {
        const int cidx = h * 32 + j2 * 4 + tg;    // f16x2 units
        Ctx2[(size_t)row0 * (DD / 2) + cidx] = pack_h2(o[j2][0] * inv0, o[j2][1] * inv0);
        Ctx2[(size_t)(row0 + 8) * (DD / 2) + cidx] = pack_h2(o[j2][2] * inv1, o[j2][3] * inv1);
    }
    #undef A_PREFETCH
}

// ---------------------------------------------------------------------------
extern "C" void kernel_launch(void* const* d_in, const int* in_sizes, int n_in,
                              void* d_out, int out_size) {
    const float* x  = (const float*)d_in[0];
    const float* Wq = (const float*)d_in[1];
    const float* bq = (const float*)d_in[2];
    const float* Wk = (const float*)d_in[3];
    const float* bk = (const float*)d_in[4];
    const float* Wv = (const float*)d_in[5];
    const float* bv = (const float*)d_in[6];
    const float* Wo = (const float*)d_in[7];
    const float* bo = (const float*)d_in[8];
    float* out = (float*)d_out;

    __half *xh, *ctx, *qh, *kh, *vh;
    cudaGetSymbolAddress((void**)&xh, g_xh);
    cudaGetSymbolAddress((void**)&ctx, g_ctx);
    cudaGetSymbolAddress((void**)&qh, g_qh);
    cudaGetSymbolAddress((void**)&kh, g_kh);
    cudaGetSymbolAddress((void**)&vh, g_vh);
    __half *wqT, *wkT, *wvT, *woT;
    cudaGetSymbolAddress((void**)&wqT, g_wqT);
    cudaGetSymbolAddress((void**)&wkT, g_wkT);
    cudaGetSymbolAddress((void**)&wvT, g_wvT);
    cudaGetSymbolAddress((void**)&woT, g_woT);

    // 1) input conversions
    int n4 = M_TOT * DD / 4;
    cvt4<<<(n4 + 255) / 256, 256>>>((const float4*)x, (uint32_t*)xh, n4);
    WJob jq{Wq, wqT}, jk{Wk, wkT}, jv{Wv, wvT}, jo{Wo, woT};
    cvt_wT4<<<dim3(DD / 32, DD / 32, 4), dim3(32, 8)>>>(jq, jk, jv, jo);

    // 2) fused QKV projection (all 1-term; Q pre-scaled by 0.125*log2(e))
    cudaFuncSetAttribute(gemm_qkv, cudaFuncAttributeMaxDynamicSharedMemorySize, SMEM_GEMM);
    cudaFuncSetAttribute(gemm_hmma, cudaFuncAttributeMaxDynamicSharedMemorySize, SMEM_GEMM);
    QKVJob job;
    job.bT[0] = wqT; job.bias[0] = bq; job.out[0] = (uint32_t*)qh;
    job.scale[0] = 0.125f * 1.44269504f;
    job.bT[1] = wkT; job.bias[1] = bk; job.out[1] = (uint32_t*)kh;
    job.scale[1] = 1.0f;
    job.bT[2] = wvT; job.bias[2] = bv; job.out[2] = (uint32_t*)vh;
    job.scale[2] = 1.0f;
    dim3 gq(3 * DD / CTA_N, M_TOT / CTA_M);   // (24, 32) = 768 CTAs
    gemm_qkv<<<gq, 256, SMEM_GEMM>>>(xh, job, M_TOT, DD, DD);

    // 3) attention -> ctx plain fp16
    cudaFuncSetAttribute(attn_hmma, cudaFuncAttributeMaxDynamicSharedMemorySize, SMEM_ATTN);
    attn_hmma<<<dim3(SS / 64, HH, BB), 128, SMEM_ATTN>>>(
        qh, kh, vh, (uint32_t*)ctx);

    // 4) output projection (1-term) -> fp32 out
    dim3 gg(DD / CTA_N, M_TOT / CTA_M);
    gemm_hmma<<<gg, 256, SMEM_GEMM>>>(ctx, woT, bo, out, M_TOT, DD, DD);
}